// round 8
// baseline (speedup 1.0000x reference)
#include <cuda_runtime.h>
#include <cuda_bf16.h>
#include <cstdint>
#include <math.h>

// Problem dims
#define BB 64
#define HH 1024
#define SS 128
#define VV 32000
#define KCAT 3072      // E + H + H (emb | context | h0)
#define G4 4096        // 4*H
#define KSPLIT 6

// d_out layout (floats)
#define OUT_H1   (64*32000)
#define OUT_C1   (OUT_H1 + 64*1024)
#define OUT_ATTN (OUT_C1 + 64*1024)

// Scratch (no allocation allowed -> device globals)
__device__ __align__(16) __nv_bfloat16 g_xh[BB*KCAT];  // [b][k] hi: emb(0..1023) ctx(1024..2047) h0(2048..3071)
__device__ __align__(16) __nv_bfloat16 g_xl[BB*KCAT];  // [b][k] lo
__device__ __align__(16) __nv_bfloat16 g_h1bf[BB*HH];  // h1 bf16, [b][k] row-major
__device__ __align__(16) float g_part[KSPLIT*G4*BB];   // gates K-split partials

typedef unsigned long long ull;
__device__ __forceinline__ void mma16816(float& c0, float& c1, float& c2, float& c3,
                                         uint32_t a0, uint32_t a1, uint32_t a2, uint32_t a3,
                                         uint32_t b0, uint32_t b1){
    asm("mma.sync.aligned.m16n8k16.row.col.f32.bf16.bf16.f32 "
        "{%0,%1,%2,%3},{%4,%5,%6,%7},{%8,%9},{%0,%1,%2,%3};"
        : "+f"(c0), "+f"(c1), "+f"(c2), "+f"(c3)
        : "r"(a0), "r"(a1), "r"(a2), "r"(a3), "r"(b0), "r"(b1));
}
__device__ __forceinline__ void ldm4(uint32_t& r0, uint32_t& r1, uint32_t& r2, uint32_t& r3,
                                     uint32_t addr){
    asm volatile("ldmatrix.sync.aligned.m8n8.x4.shared.b16 {%0,%1,%2,%3}, [%4];"
        : "=r"(r0), "=r"(r1), "=r"(r2), "=r"(r3) : "r"(addr));
}
__device__ __forceinline__ uint32_t cvt2bf(float lo, float hi){
    __nv_bfloat162 h = __floats2bfloat162_rn(lo, hi);   // .x = lo (low 16 bits)
    return *(uint32_t*)&h;
}
// fp32 -> (hi, lo) bf16 split of a pair
__device__ __forceinline__ void split2(float x, float y, uint32_t& hi, uint32_t& lo){
    __nv_bfloat162 h = __floats2bfloat162_rn(x, y);
    float rx = x - __bfloat162float(h.x);
    float ry = y - __bfloat162float(h.y);
    __nv_bfloat162 l = __floats2bfloat162_rn(rx, ry);
    hi = *(uint32_t*)&h; lo = *(uint32_t*)&l;
}
__device__ __forceinline__ void splitbf(float x, __nv_bfloat16* ph, __nv_bfloat16* pl){
    __nv_bfloat16 h = __float2bfloat16(x);
    *ph = h;
    *pl = __float2bfloat16(x - __bfloat162float(h));
}

// ---------------------------------------------------------------------------
// Kernel 1: attention (scores, softmax, context) + emb gather + bf16 hi/lo prep
// grid 64, 256 threads
// ---------------------------------------------------------------------------
__global__ void attn_kernel(const int* __restrict__ input_batch, const float* __restrict__ prev_h,
                            const float* __restrict__ enc, const float* __restrict__ emb,
                            const float* __restrict__ attn_w, const float* __restrict__ attn_b,
                            float* __restrict__ out)
{
    __shared__ float sw2[1024];
    __shared__ float sweights[128];
    __shared__ float red[40];
    const int b = blockIdx.x, tid = threadIdx.x, lane = tid & 31, warp = tid >> 5;
    const int tok = input_batch[b];
    __nv_bfloat16* xh = g_xh + (size_t)b*KCAT;
    __nv_bfloat16* xl = g_xl + (size_t)b*KCAT;

    float hacc = 0.f;
    for (int i = tid; i < 1024; i += 256){
        float h0v = prev_h[(size_t)b*1024 + i];
        hacc += attn_w[i] * h0v;
        sw2[i] = attn_w[1024 + i];
        splitbf(h0v, xh + 2048 + i, xl + 2048 + i);
        float xe = emb[(size_t)tok*1024 + i];
        splitbf(xe, xh + i, xl + i);
    }
    #pragma unroll
    for (int o=16;o;o>>=1) hacc += __shfl_xor_sync(0xffffffffu, hacc, o);
    if (lane==0) red[warp] = hacc;
    __syncthreads();
    if (tid==0){ float s=0.f; for (int w=0;w<8;w++) s+=red[w]; red[32] = s + attn_b[0]; }
    __syncthreads();
    const float hpb = red[32];

    const float* encb = enc + (size_t)b*SS*HH;
    for (int s = warp; s < 128; s += 8){
        const float* ep = encb + (size_t)s*1024;
        float acc = 0.f;
        #pragma unroll 8
        for (int j=0;j<32;j++){ int i = lane + j*32; acc += ep[i]*sw2[i]; }
        #pragma unroll
        for (int o=16;o;o>>=1) acc += __shfl_xor_sync(0xffffffffu, acc, o);
        if (lane==0) sweights[s] = acc + hpb;
    }
    __syncthreads();

    float sc = (tid<128) ? sweights[tid] : -3.0e38f;
    float m = sc;
    #pragma unroll
    for (int o=16;o;o>>=1) m = fmaxf(m, __shfl_xor_sync(0xffffffffu, m, o));
    if (lane==0) red[warp] = m;
    __syncthreads();
    if (tid==0){ float mm=red[0]; for (int w=1;w<8;w++) mm=fmaxf(mm,red[w]); red[33]=mm; }
    __syncthreads();
    m = red[33];
    float e = (tid<128) ? __expf(sc - m) : 0.f;
    float z = e;
    #pragma unroll
    for (int o=16;o;o>>=1) z += __shfl_xor_sync(0xffffffffu, z, o);
    if (lane==0) red[warp] = z;
    __syncthreads();
    if (tid==0){ float s=0.f; for (int w=0;w<8;w++) s+=red[w]; red[34]=s; }
    __syncthreads();
    const float Z = red[34];
    if (tid < 128){
        float w = e / Z;
        sweights[tid] = w;
        out[OUT_ATTN + b*128 + tid] = w;
    }
    __syncthreads();

    const int h4 = tid*4;
    float4 a4 = {0.f,0.f,0.f,0.f};
    for (int s=0;s<128;s++){
        float w = sweights[s];
        float4 ev = *(const float4*)(encb + (size_t)s*1024 + h4);
        a4.x += w*ev.x; a4.y += w*ev.y; a4.z += w*ev.z; a4.w += w*ev.w;
    }
    splitbf(a4.x, xh + 1024 + h4 + 0, xl + 1024 + h4 + 0);
    splitbf(a4.y, xh + 1024 + h4 + 1, xl + 1024 + h4 + 1);
    splitbf(a4.z, xh + 1024 + h4 + 2, xl + 1024 + h4 + 2);
    splitbf(a4.w, xh + 1024 + h4 + 3, xl + 1024 + h4 + 3);
}

// ---------------------------------------------------------------------------
// Kernel 2: gates GEMM via split-bf16 tensor MMA (fp32-class accuracy)
// grid (32, 6), 256 threads. Tile M=128(g) x N=64(b), K=512/block, chunks of 32.
// gates = [W_ih | W_hh] @ [emb|ctx|h0]^T ; 3 MMAs per step: hh + hl + lh.
// ---------------------------------------------------------------------------
#define GA_P 40   // bf16 pitch (80B rows): ldmatrix + LDS conflict-free
__global__ __launch_bounds__(256) void gates_gemm_mma(const float* __restrict__ W_ih,
                                                      const float* __restrict__ W_hh)
{
    __shared__ __align__(16) __nv_bfloat16 Ah[128*GA_P];  // 10240 B
    __shared__ __align__(16) __nv_bfloat16 Al[128*GA_P];
    __shared__ __align__(16) __nv_bfloat16 Bh[64*GA_P];   // 5120 B
    __shared__ __align__(16) __nv_bfloat16 Bl[64*GA_P];
    const int tid = threadIdx.x, lane = tid & 31, warp = tid >> 5;
    const int gid = lane >> 2, tg = lane & 3;
    const int g0 = blockIdx.x * 128;
    const int ky = blockIdx.y;
    const bool ih = (ky < 4);

    const int r = tid >> 1, hh = tid & 1;          // A: row r, 16 cols at half hh
    const float* Ap = ih ? (W_ih + (size_t)(g0 + r)*2048 + ky*512 + hh*16)
                         : (W_hh + (size_t)(g0 + r)*1024 + (ky-4)*512 + hh*16);
    const int kb = ky*512;
    const __nv_bfloat16* Bgh = g_xh + (size_t)(tid>>2)*KCAT + kb + (tid&3)*8;
    const __nv_bfloat16* Bgl = g_xl + (size_t)(tid>>2)*KCAT + kb + (tid&3)*8;

    const uint32_t ah_b = (uint32_t)__cvta_generic_to_shared(Ah);
    const uint32_t al_b = (uint32_t)__cvta_generic_to_shared(Al);

    float acc[8][4];
    #pragma unroll
    for (int nt=0; nt<8; nt++){ acc[nt][0]=0.f; acc[nt][1]=0.f; acc[nt][2]=0.f; acc[nt][3]=0.f; }

    float4 pa[4]; uint4 pbh, pbl;
    #pragma unroll
    for (int j=0;j<4;j++) pa[j] = *(const float4*)(Ap + j*4);
    pbh = *(const uint4*)Bgh;
    pbl = *(const uint4*)Bgl;

    const int NT = 512/32;  // 16
    for (int t=0; t<NT; ++t){
        __syncthreads();
        #pragma unroll
        for (int j=0;j<4;j++){
            uint32_t h0,l0,h1,l1;
            split2(pa[j].x, pa[j].y, h0, l0);
            split2(pa[j].z, pa[j].w, h1, l1);
            *(uint2*)(Ah + r*GA_P + hh*16 + j*4) = make_uint2(h0, h1);
            *(uint2*)(Al + r*GA_P + hh*16 + j*4) = make_uint2(l0, l1);
        }
        *(uint4*)(Bh + (tid>>2)*GA_P + (tid&3)*8) = pbh;
        *(uint4*)(Bl + (tid>>2)*GA_P + (tid&3)*8) = pbl;
        __syncthreads();
        if (t+1 < NT){
            const float* An = Ap + (t+1)*32;
            #pragma unroll
            for (int j=0;j<4;j++) pa[j] = *(const float4*)(An + j*4);
            pbh = *(const uint4*)(Bgh + (t+1)*32);
            pbl = *(const uint4*)(Bgl + (t+1)*32);
        }
        const uint32_t aoff = (uint32_t)((warp*16 + (lane & 15))*GA_P + ((lane>>4)*8)) * 2;
        #pragma unroll
        for (int s=0; s<2; ++s){
            uint32_t ah0,ah1,ah2,ah3, al0,al1,al2,al3;
            ldm4(ah0,ah1,ah2,ah3, ah_b + aoff + s*32);
            ldm4(al0,al1,al2,al3, al_b + aoff + s*32);
            #pragma unroll
            for (int nt=0; nt<8; nt++){
                const int bo = (nt*8 + gid)*GA_P + s*16 + tg*2;
                uint32_t bh0 = *(const uint32_t*)(Bh + bo);
                uint32_t bh1 = *(const uint32_t*)(Bh + bo + 8);
                uint32_t bl0 = *(const uint32_t*)(Bl + bo);
                uint32_t bl1 = *(const uint32_t*)(Bl + bo + 8);
                mma16816(acc[nt][0],acc[nt][1],acc[nt][2],acc[nt][3], ah0,ah1,ah2,ah3, bh0,bh1);
                mma16816(acc[nt][0],acc[nt][1],acc[nt][2],acc[nt][3], ah0,ah1,ah2,ah3, bl0,bl1);
                mma16816(acc[nt][0],acc[nt][1],acc[nt][2],acc[nt][3], al0,al1,al2,al3, bh0,bh1);
            }
        }
    }
    // write partials: rows m0/m1 (g), cols n (b), float2 contiguous
    float* P = g_part + (size_t)ky*G4*64;
    const int m0 = g0 + warp*16 + gid, m1 = m0 + 8;
    #pragma unroll
    for (int nt=0; nt<8; nt++){
        const int n0 = nt*8 + tg*2;
        *(float2*)&P[(size_t)m0*64 + n0] = make_float2(acc[nt][0], acc[nt][1]);
        *(float2*)&P[(size_t)m1*64 + n0] = make_float2(acc[nt][2], acc[nt][3]);
    }
}

// ---------------------------------------------------------------------------
// Kernel 3: K-split reduce + biases + LSTM cell (+ bf16 h1 for tensor GEMM)
// ---------------------------------------------------------------------------
__global__ void lstm_kernel(const float* __restrict__ prev_c, const int* __restrict__ lengths,
                            const float* __restrict__ b_ih, const float* __restrict__ b_hh,
                            float* __restrict__ out)
{
    const int id = blockIdx.x*256 + threadIdx.x;   // 0..65535
    const int b = id & 63, h = id >> 6;
    float s[4] = {0.f,0.f,0.f,0.f};
    #pragma unroll
    for (int ky=0; ky<KSPLIT; ++ky){
        const float* P = g_part + (size_t)ky*G4*64;
        #pragma unroll
        for (int g=0; g<4; ++g) s[g] += P[(size_t)(g*1024 + h)*64 + b];
    }
    #pragma unroll
    for (int g=0; g<4; ++g) s[g] += b_ih[g*1024+h] + b_hh[g*1024+h];
    float ig = 1.f/(1.f + __expf(-s[0]));
    float fg = 1.f/(1.f + __expf(-s[1]));
    float gg = tanhf(s[2]);
    float og = 1.f/(1.f + __expf(-s[3]));
    float c0 = prev_c[(size_t)b*HH + h];
    float c1 = fg*c0 + ig*gg;
    float h1 = og*tanhf(c1);
    if (lengths[b] == 0){ c1 = 0.f; h1 = 0.f; }
    out[OUT_H1 + b*HH + h] = h1;
    out[OUT_C1 + b*HH + h] = c1;
    g_h1bf[(size_t)b*HH + h] = __float2bfloat16(h1);
}

// ---------------------------------------------------------------------------
// Kernel 4: logits GEMM via bf16 mma. grid 250, 256 thr.
// Tile M=128(v) x N=64(b), K-chunks of 64, single smem stage + deep reg prefetch.
// ---------------------------------------------------------------------------
#define L_AP 72                      // bf16 pitch (144B rows): conflict-free
#define L_ABYTES (128*L_AP*2)        // 18432
#define SC_PITCH 132                 // epilogue float pitch
__global__ __launch_bounds__(256) void logits_gemm_mma(const float* __restrict__ W_out,
                                                       const float* __restrict__ b_out,
                                                       float* __restrict__ out)
{
    __shared__ __align__(16) unsigned char sm[64*SC_PITCH*4];   // 33792 >= 18432+9216
    __nv_bfloat16* As = (__nv_bfloat16*)sm;
    __nv_bfloat16* Bs = (__nv_bfloat16*)(sm + L_ABYTES);
    const int tid = threadIdx.x, lane = tid & 31, warp = tid >> 5;
    const int gid = lane >> 2, tg = lane & 3;
    const int vb = blockIdx.x * 128;
    const uint32_t as_b = (uint32_t)__cvta_generic_to_shared(As);

    const int r = tid >> 1, half = tid & 1;        // A: row r, 32 cols at half
    const float* Ap = W_out + (size_t)(vb + r)*HH + half*32;
    const __nv_bfloat16* Bg = g_h1bf + (size_t)(tid>>2)*HH + (tid&3)*16;

    float acc[8][4];
    #pragma unroll
    for (int nt=0; nt<8; nt++){ acc[nt][0]=0.f; acc[nt][1]=0.f; acc[nt][2]=0.f; acc[nt][3]=0.f; }

    float4 pa[8]; uint4 pb0, pb1;
    #pragma unroll
    for (int j=0;j<8;j++) pa[j] = *(const float4*)(Ap + j*4);
    pb0 = *(const uint4*)Bg;
    pb1 = *(const uint4*)(Bg + 8);

    const int NCH = HH / 64;   // 16
    for (int t=0; t<NCH; ++t){
        __syncthreads();
        #pragma unroll
        for (int j=0;j<4;j++){
            uint4 v;
            v.x = cvt2bf(pa[2*j].x,   pa[2*j].y);
            v.y = cvt2bf(pa[2*j].z,   pa[2*j].w);
            v.z = cvt2bf(pa[2*j+1].x, pa[2*j+1].y);
            v.w = cvt2bf(pa[2*j+1].z, pa[2*j+1].w);
            *(uint4*)(As + r*L_AP + half*32 + j*8) = v;
        }
        *(uint4*)(Bs + (tid>>2)*L_AP + (tid&3)*16)     = pb0;
        *(uint4*)(Bs + (tid>>2)*L_AP + (tid&3)*16 + 8) = pb1;
        __syncthreads();
        if (t+1 < NCH){
            const float* An = Ap + (t+1)*64;
            #pragma unroll
            for (int j=0;j<8;j++) pa[j] = *(const float4*)(An + j*4);
            pb0 = *(const uint4*)(Bg + (t+1)*64);
            pb1 = *(const uint4*)(Bg + (t+1)*64 + 8);
        }
        const uint32_t abase = as_b + (uint32_t)((warp*16 + (lane & 15))*L_AP + ((lane>>4)*8)) * 2;
        #pragma unroll
        for (int s=0; s<4; ++s){
            uint32_t a0,a1,a2,a3;
            ldm4(a0,a1,a2,a3, abase + s*32);
            #pragma unroll
            for (int nt=0; nt<8; nt++){
                const int bo = (nt*8 + gid)*L_AP + s*16 + tg*2;
                uint32_t b0 = *(const uint32_t*)(Bs + bo);
                uint32_t b1 = *(const uint32_t*)(Bs + bo + 8);
                mma16816(acc[nt][0],acc[nt][1],acc[nt][2],acc[nt][3], a0,a1,a2,a3, b0,b1);
            }
        }
    }
    __syncthreads();   // compute done before aliasing smem

    float* scf = (float*)sm;   // [64][SC_PITCH]
    const int m0 = warp*16 + gid, m1 = m0 + 8;
    const float bo0 = b_out[vb + m0];
    const float bo1 = b_out[vb + m1];
    #pragma unroll
    for (int nt=0; nt<8; nt++){
        const int n0 = nt*8 + tg*2;
        scf[(size_t)(n0  )*SC_PITCH + m0] = acc[nt][0] + bo0;
        scf[(size_t)(n0+1)*SC_PITCH + m0] = acc[nt][1] + bo0;
        scf[(size_t)(n0  )*SC_PITCH + m1] = acc[nt][2] + bo1;
        scf[(size_t)(n0+1)*SC_PITCH + m1] = acc[nt][3] + bo1;
    }
    __syncthreads();
    const int b = tid>>2, q = tid&3;
    float* orow = out + (size_t)b*VV + vb;
    #pragma unroll
    for (int i=0;i<8;i++){
        const int f = q*8 + i;
        *(float4*)&orow[f*4] = *(const float4*)&scf[(size_t)b*SC_PITCH + f*4];
    }
}

// ---------------------------------------------------------------------------
// Kernel 5: in-place log_softmax per batch row over V=32000. 64 blocks x 1024.
// float4 vectorized.
// ---------------------------------------------------------------------------
__global__ __launch_bounds__(1024) void logsoftmax_kernel(float* __restrict__ out)
{
    __shared__ float red[33];
    const int b = blockIdx.x, tid = threadIdx.x, lane = tid & 31, warp = tid >> 5;
    float* row = out + (size_t)b*VV;
    float4 vals[8];
    float m = -3.0e38f;
    #pragma unroll
    for (int j=0;j<8;j++){
        int idx = tid*4 + j*4096;
        if (idx < VV){
            vals[j] = *(const float4*)&row[idx];
            m = fmaxf(m, fmaxf(fmaxf(vals[j].x, vals[j].y), fmaxf(vals[j].z, vals[j].w)));
        } else {
            vals[j] = make_float4(-3.0e38f,-3.0e38f,-3.0e38f,-3.0e38f);
        }
    }
    #pragma unroll
    for (int o=16;o;o>>=1) m = fmaxf(m, __shfl_xor_sync(0xffffffffu, m, o));
    if (lane==0) red[warp] = m;
    __syncthreads();
    if (warp==0){
        float v = red[lane];
        #pragma unroll
        for (int o=16;o;o>>=1) v = fmaxf(v, __shfl_xor_sync(0xffffffffu, v, o));
        if (lane==0) red[32] = v;
    }
    __syncthreads();
    m = red[32];
    __syncthreads();
    float z = 0.f;
    #pragma unroll
    for (int j=0;j<8;j++){
        int idx = tid*4 + j*4096;
        if (idx < VV)
            z += __expf(vals[j].x - m) + __expf(vals[j].y - m)
               + __expf(vals[j].z - m) + __expf(vals[j].w - m);
    }
    #pragma unroll
    for (int o=16;o;o>>=1) z += __shfl_xor_sync(0xffffffffu, z, o);
    if (lane==0) red[warp] = z;
    __syncthreads();
    if (warp==0){
        float v = red[lane];
        #pragma unroll
        for (int o=16;o;o>>=1) v += __shfl_xor_sync(0xffffffffu, v, o);
        if (lane==0) red[32] = v;
    }
    __syncthreads();
    const float lse = m + logf(red[32]);
    #pragma unroll
    for (int j=0;j<8;j++){
        int idx = tid*4 + j*4096;
        if (idx < VV){
            float4 o4 = make_float4(vals[j].x - lse, vals[j].y - lse,
                                    vals[j].z - lse, vals[j].w - lse);
            *(float4*)&row[idx] = o4;
        }
    }
}

// ---------------------------------------------------------------------------
extern "C" void kernel_launch(void* const* d_in, const int* in_sizes, int n_in,
                              void* d_out, int out_size)
{
    const int*   input_batch = (const int*)  d_in[0];
    const float* prev_h      = (const float*)d_in[1];
    const float* prev_c      = (const float*)d_in[2];
    const float* enc         = (const float*)d_in[3];
    const int*   lengths     = (const int*)  d_in[4];
    const float* emb         = (const float*)d_in[5];
    const float* attn_w      = (const float*)d_in[6];
    const float* attn_b      = (const float*)d_in[7];
    const float* W_ih        = (const float*)d_in[8];
    const float* W_hh        = (const float*)d_in[9];
    const float* b_ih        = (const float*)d_in[10];
    const float* b_hh        = (const float*)d_in[11];
    const float* W_out       = (const float*)d_in[12];
    const float* b_out       = (const float*)d_in[13];
    float* out = (float*)d_out;

    attn_kernel<<<64, 256>>>(input_batch, prev_h, enc, emb, attn_w, attn_b, out);
    gates_gemm_mma<<<dim3(32, KSPLIT), 256>>>(W_ih, W_hh);
    lstm_kernel<<<256, 256>>>(prev_c, lengths, b_ih, b_hh, out);
    logits_gemm_mma<<<250, 256>>>(W_out, b_out, out);
    logsoftmax_kernel<<<64, 1024>>>(out);
}

// round 10
// speedup vs baseline: 1.4244x; 1.4244x over previous
#include <cuda_runtime.h>
#include <cuda_bf16.h>
#include <cstdint>
#include <math.h>

// Problem dims
#define BB 64
#define HH 1024
#define SS 128
#define VV 32000
#define KCAT 3072      // E + H + H (emb | context | h0)
#define G4 4096        // 4*H
#define KSPLIT 6

// d_out layout (floats)
#define OUT_H1   (64*32000)
#define OUT_C1   (OUT_H1 + 64*1024)
#define OUT_ATTN (OUT_C1 + 64*1024)

// Scratch (no allocation allowed -> device globals)
__device__ __align__(16) __nv_bfloat16 g_xh[BB*KCAT];  // [b][k] hi: emb|ctx|h0
__device__ __align__(16) __nv_bfloat16 g_xl[BB*KCAT];  // [b][k] lo
__device__ __align__(16) __nv_bfloat16 g_h1bf[BB*HH];  // h1 bf16, [b][k]
__device__ __align__(16) float g_part[KSPLIT*G4*BB];   // gates K-split partials
__device__ __align__(16) float g_scores[BB*SS];        // attention scores

typedef unsigned long long ull;
__device__ __forceinline__ void mma16816(float& c0, float& c1, float& c2, float& c3,
                                         uint32_t a0, uint32_t a1, uint32_t a2, uint32_t a3,
                                         uint32_t b0, uint32_t b1){
    asm("mma.sync.aligned.m16n8k16.row.col.f32.bf16.bf16.f32 "
        "{%0,%1,%2,%3},{%4,%5,%6,%7},{%8,%9},{%0,%1,%2,%3};"
        : "+f"(c0), "+f"(c1), "+f"(c2), "+f"(c3)
        : "r"(a0), "r"(a1), "r"(a2), "r"(a3), "r"(b0), "r"(b1));
}
__device__ __forceinline__ void ldm4(uint32_t& r0, uint32_t& r1, uint32_t& r2, uint32_t& r3,
                                     uint32_t addr){
    asm volatile("ldmatrix.sync.aligned.m8n8.x4.shared.b16 {%0,%1,%2,%3}, [%4];"
        : "=r"(r0), "=r"(r1), "=r"(r2), "=r"(r3) : "r"(addr));
}
__device__ __forceinline__ uint32_t cvt2bf(float lo, float hi){
    __nv_bfloat162 h = __floats2bfloat162_rn(lo, hi);   // .x = lo
    return *(uint32_t*)&h;
}
__device__ __forceinline__ void split2(float x, float y, uint32_t& hi, uint32_t& lo){
    __nv_bfloat162 h = __floats2bfloat162_rn(x, y);
    float rx = x - __bfloat162float(h.x);
    float ry = y - __bfloat162float(h.y);
    __nv_bfloat162 l = __floats2bfloat162_rn(rx, ry);
    hi = *(uint32_t*)&h; lo = *(uint32_t*)&l;
}
__device__ __forceinline__ void splitbf(float x, __nv_bfloat16* ph, __nv_bfloat16* pl){
    __nv_bfloat16 h = __float2bfloat16(x);
    *ph = h;
    *pl = __float2bfloat16(x - __bfloat162float(h));
}
__device__ __forceinline__ void cpa16(uint32_t dst, const void* src){
    asm volatile("cp.async.cg.shared.global [%0], [%1], 16;" :: "r"(dst), "l"(src));
}
#define CPA_COMMIT() asm volatile("cp.async.commit_group;" ::: "memory")
#define CPA_WAIT(n)  asm volatile("cp.async.wait_group %0;" :: "n"(n) : "memory")

// ---------------------------------------------------------------------------
// Kernel 1: scores + emb/h0 bf16 prep. grid (64, 4), 256 thr.
// block (b,q): h_part(b), scores s in [q*32, q*32+32), splits for chunk q.
// ---------------------------------------------------------------------------
__global__ void scores_kernel(const int* __restrict__ input_batch, const float* __restrict__ prev_h,
                              const float* __restrict__ enc, const float* __restrict__ emb,
                              const float* __restrict__ attn_w, const float* __restrict__ attn_b)
{
    __shared__ float sw2[1024];
    __shared__ float red[40];
    const int b = blockIdx.x, q = blockIdx.y;
    const int tid = threadIdx.x, lane = tid & 31, warp = tid >> 5;
    const int tok = input_batch[b];
    __nv_bfloat16* xh = g_xh + (size_t)b*KCAT;
    __nv_bfloat16* xl = g_xl + (size_t)b*KCAT;

    float hacc = 0.f;
    #pragma unroll
    for (int k = 0; k < 4; k++){
        const int i = tid + k*256;
        float h0v = prev_h[(size_t)b*1024 + i];
        hacc += attn_w[i] * h0v;
        sw2[i] = attn_w[1024 + i];
        if (k == q){
            splitbf(h0v, xh + 2048 + i, xl + 2048 + i);
            float xe = emb[(size_t)tok*1024 + i];
            splitbf(xe, xh + i, xl + i);
        }
    }
    #pragma unroll
    for (int o=16;o;o>>=1) hacc += __shfl_xor_sync(0xffffffffu, hacc, o);
    if (lane==0) red[warp] = hacc;
    __syncthreads();
    if (tid==0){ float s=0.f; for (int w=0;w<8;w++) s+=red[w]; red[32] = s + attn_b[0]; }
    __syncthreads();
    const float hpb = red[32];

    const float* encb = enc + (size_t)b*SS*HH;
    #pragma unroll
    for (int s4 = 0; s4 < 4; s4++){
        const int s = q*32 + warp*4 + s4;
        const float* ep = encb + (size_t)s*1024;
        float acc = 0.f;
        #pragma unroll 8
        for (int j=0;j<32;j++){ int i = lane + j*32; acc += ep[i]*sw2[i]; }
        #pragma unroll
        for (int o=16;o;o>>=1) acc += __shfl_xor_sync(0xffffffffu, acc, o);
        if (lane==0) g_scores[b*128 + s] = acc + hpb;
    }
}

// ---------------------------------------------------------------------------
// Kernel 2: softmax (redundant, cheap) + context slice. grid (64, 4), 256 thr.
// block (b,hc): context for h in [hc*256, hc*256+256).
// ---------------------------------------------------------------------------
__global__ void ctx_kernel(const float* __restrict__ enc, float* __restrict__ out)
{
    __shared__ float sweights[128];
    __shared__ float red[40];
    const int b = blockIdx.x, hc = blockIdx.y;
    const int tid = threadIdx.x, lane = tid & 31, warp = tid >> 5;

    float sc = (tid<128) ? g_scores[b*128 + tid] : -3.0e38f;
    float m = sc;
    #pragma unroll
    for (int o=16;o;o>>=1) m = fmaxf(m, __shfl_xor_sync(0xffffffffu, m, o));
    if (lane==0) red[warp] = m;
    __syncthreads();
    if (tid==0){ float mm=red[0]; for (int w=1;w<8;w++) mm=fmaxf(mm,red[w]); red[33]=mm; }
    __syncthreads();
    m = red[33];
    float e = (tid<128) ? __expf(sc - m) : 0.f;
    float z = e;
    #pragma unroll
    for (int o=16;o;o>>=1) z += __shfl_xor_sync(0xffffffffu, z, o);
    if (lane==0) red[warp] = z;
    __syncthreads();
    if (tid==0){ float s=0.f; for (int w=0;w<8;w++) s+=red[w]; red[34]=s; }
    __syncthreads();
    const float Z = red[34];
    if (tid < 128){
        float w = e / Z;
        sweights[tid] = w;
        if (hc == 0) out[OUT_ATTN + b*128 + tid] = w;
    }
    __syncthreads();

    const int h = hc*256 + tid;
    const float* ecol = enc + (size_t)b*SS*HH + h;
    float acc = 0.f;
    #pragma unroll 4
    for (int s=0; s<128; s++) acc += sweights[s] * ecol[(size_t)s*1024];
    splitbf(acc, g_xh + (size_t)b*KCAT + 1024 + h, g_xl + (size_t)b*KCAT + 1024 + h);
}

// ---------------------------------------------------------------------------
// Kernel 3: gates GEMM via split-bf16 tensor MMA (proven round-8 version)
// ---------------------------------------------------------------------------
#define GA_P 40
__global__ __launch_bounds__(256) void gates_gemm_mma(const float* __restrict__ W_ih,
                                                      const float* __restrict__ W_hh)
{
    __shared__ __align__(16) __nv_bfloat16 Ah[128*GA_P];
    __shared__ __align__(16) __nv_bfloat16 Al[128*GA_P];
    __shared__ __align__(16) __nv_bfloat16 Bh[64*GA_P];
    __shared__ __align__(16) __nv_bfloat16 Bl[64*GA_P];
    const int tid = threadIdx.x, lane = tid & 31, warp = tid >> 5;
    const int gid = lane >> 2, tg = lane & 3;
    const int g0 = blockIdx.x * 128;
    const int ky = blockIdx.y;
    const bool ih = (ky < 4);

    const int r = tid >> 1, hh = tid & 1;
    const float* Ap = ih ? (W_ih + (size_t)(g0 + r)*2048 + ky*512 + hh*16)
                         : (W_hh + (size_t)(g0 + r)*1024 + (ky-4)*512 + hh*16);
    const int kb = ky*512;
    const __nv_bfloat16* Bgh = g_xh + (size_t)(tid>>2)*KCAT + kb + (tid&3)*8;
    const __nv_bfloat16* Bgl = g_xl + (size_t)(tid>>2)*KCAT + kb + (tid&3)*8;

    const uint32_t ah_b = (uint32_t)__cvta_generic_to_shared(Ah);
    const uint32_t al_b = (uint32_t)__cvta_generic_to_shared(Al);

    float acc[8][4];
    #pragma unroll
    for (int nt=0; nt<8; nt++){ acc[nt][0]=0.f; acc[nt][1]=0.f; acc[nt][2]=0.f; acc[nt][3]=0.f; }

    float4 pa[4]; uint4 pbh, pbl;
    #pragma unroll
    for (int j=0;j<4;j++) pa[j] = *(const float4*)(Ap + j*4);
    pbh = *(const uint4*)Bgh;
    pbl = *(const uint4*)Bgl;

    const int NT = 512/32;
    for (int t=0; t<NT; ++t){
        __syncthreads();
        #pragma unroll
        for (int j=0;j<4;j++){
            uint32_t h0,l0,h1,l1;
            split2(pa[j].x, pa[j].y, h0, l0);
            split2(pa[j].z, pa[j].w, h1, l1);
            *(uint2*)(Ah + r*GA_P + hh*16 + j*4) = make_uint2(h0, h1);
            *(uint2*)(Al + r*GA_P + hh*16 + j*4) = make_uint2(l0, l1);
        }
        *(uint4*)(Bh + (tid>>2)*GA_P + (tid&3)*8) = pbh;
        *(uint4*)(Bl + (tid>>2)*GA_P + (tid&3)*8) = pbl;
        __syncthreads();
        if (t+1 < NT){
            const float* An = Ap + (t+1)*32;
            #pragma unroll
            for (int j=0;j<4;j++) pa[j] = *(const float4*)(An + j*4);
            pbh = *(const uint4*)(Bgh + (t+1)*32);
            pbl = *(const uint4*)(Bgl + (t+1)*32);
        }
        const uint32_t aoff = (uint32_t)((warp*16 + (lane & 15))*GA_P + ((lane>>4)*8)) * 2;
        #pragma unroll
        for (int s=0; s<2; ++s){
            uint32_t ah0,ah1,ah2,ah3, al0,al1,al2,al3;
            ldm4(ah0,ah1,ah2,ah3, ah_b + aoff + s*32);
            ldm4(al0,al1,al2,al3, al_b + aoff + s*32);
            #pragma unroll
            for (int nt=0; nt<8; nt++){
                const int bo = (nt*8 + gid)*GA_P + s*16 + tg*2;
                uint32_t bh0 = *(const uint32_t*)(Bh + bo);
                uint32_t bh1 = *(const uint32_t*)(Bh + bo + 8);
                uint32_t bl0 = *(const uint32_t*)(Bl + bo);
                uint32_t bl1 = *(const uint32_t*)(Bl + bo + 8);
                mma16816(acc[nt][0],acc[nt][1],acc[nt][2],acc[nt][3], ah0,ah1,ah2,ah3, bh0,bh1);
                mma16816(acc[nt][0],acc[nt][1],acc[nt][2],acc[nt][3], ah0,ah1,ah2,ah3, bl0,bl1);
                mma16816(acc[nt][0],acc[nt][1],acc[nt][2],acc[nt][3], al0,al1,al2,al3, bh0,bh1);
            }
        }
    }
    float* P = g_part + (size_t)ky*G4*64;
    const int m0 = g0 + warp*16 + gid, m1 = m0 + 8;
    #pragma unroll
    for (int nt=0; nt<8; nt++){
        const int n0 = nt*8 + tg*2;
        *(float2*)&P[(size_t)m0*64 + n0] = make_float2(acc[nt][0], acc[nt][1]);
        *(float2*)&P[(size_t)m1*64 + n0] = make_float2(acc[nt][2], acc[nt][3]);
    }
}

// ---------------------------------------------------------------------------
// Kernel 4: K-split reduce + biases + LSTM cell
// ---------------------------------------------------------------------------
__global__ void lstm_kernel(const float* __restrict__ prev_c, const int* __restrict__ lengths,
                            const float* __restrict__ b_ih, const float* __restrict__ b_hh,
                            float* __restrict__ out)
{
    const int id = blockIdx.x*256 + threadIdx.x;
    const int b = id & 63, h = id >> 6;
    float s[4] = {0.f,0.f,0.f,0.f};
    #pragma unroll
    for (int ky=0; ky<KSPLIT; ++ky){
        const float* P = g_part + (size_t)ky*G4*64;
        #pragma unroll
        for (int g=0; g<4; ++g) s[g] += P[(size_t)(g*1024 + h)*64 + b];
    }
    #pragma unroll
    for (int g=0; g<4; ++g) s[g] += b_ih[g*1024+h] + b_hh[g*1024+h];
    float ig = 1.f/(1.f + __expf(-s[0]));
    float fg = 1.f/(1.f + __expf(-s[1]));
    float gg = tanhf(s[2]);
    float og = 1.f/(1.f + __expf(-s[3]));
    float c0 = prev_c[(size_t)b*HH + h];
    float c1 = fg*c0 + ig*gg;
    float h1 = og*tanhf(c1);
    if (lengths[b] == 0){ c1 = 0.f; h1 = 0.f; }
    out[OUT_H1 + b*HH + h] = h1;
    out[OUT_C1 + b*HH + h] = c1;
    g_h1bf[(size_t)b*HH + h] = __float2bfloat16(h1);
}

// ---------------------------------------------------------------------------
// Kernel 5: logits GEMM, cp.async 3-stage pipeline.
// A staged fp32 (128 x 32 per chunk, pitch 40 fl), B staged bf16 (64 x 32, pitch 40 bf).
// Fragment-layout LDS.64 reads + cvt to bf16, mma m16n8k16.
// grid 250, 256 thr, dynamic smem 76800.
// ---------------------------------------------------------------------------
#define L_STAGES 3
#define L_ABYTES2 20480              // 128 rows * 160B (pitch 40 floats)
#define L_STBYTES 25600              // A (20480) + B (64*80 = 5120)
#define SC_PITCH 132
#define L_SMEM 76800                 // 3*25600; >= 64*132*4 epilogue

extern "C" __global__ __launch_bounds__(256) void logits_gemm_ca(
    const float* __restrict__ W_out, const float* __restrict__ b_out, float* __restrict__ out)
{
    extern __shared__ __align__(16) unsigned char dyn[];
    const int tid = threadIdx.x, lane = tid & 31, warp = tid >> 5;
    const int gid = lane >> 2, tg = lane & 3;
    const int vb = blockIdx.x * 128;
    const uint32_t smb = (uint32_t)__cvta_generic_to_shared(dyn);

    // staging thread roles
    const int arow = tid >> 1, aseg = tid & 1;     // A: 2 thr/row, 64B each
    const int brow = tid >> 2, bseg = tid & 3;     // B: 4 thr/row, 16B each
    const float* Asrc = W_out + (size_t)(vb + arow)*HH + aseg*16;
    const __nv_bfloat16* Bsrc = g_h1bf + (size_t)brow*HH + bseg*8;

    const int NCH = HH/32;   // 32

    // prologue: stage chunks 0,1
    #pragma unroll
    for (int t=0; t<L_STAGES-1; ++t){
        const uint32_t st = smb + t*L_STBYTES;
        #pragma unroll
        for (int j=0;j<4;j++)
            cpa16(st + arow*160 + aseg*64 + j*16, Asrc + t*32 + j*4);
        cpa16(st + L_ABYTES2 + brow*80 + bseg*16, Bsrc + t*32);
        CPA_COMMIT();
    }

    float acc[8][4];
    #pragma unroll
    for (int nt=0; nt<8; nt++){ acc[nt][0]=0.f; acc[nt][1]=0.f; acc[nt][2]=0.f; acc[nt][3]=0.f; }

    for (int t=0; t<NCH; ++t){
        CPA_WAIT(1);          // chunk t resident
        __syncthreads();      // visible to all; all threads done with chunk t-1
        // issue chunk t+2 into buffer (t+2)%3 == (t-1)%3 -- safe after sync
        if (t + L_STAGES - 1 < NCH){
            const int tn = t + L_STAGES - 1;
            const uint32_t st = smb + (tn % L_STAGES)*L_STBYTES;
            #pragma unroll
            for (int j=0;j<4;j++)
                cpa16(st + arow*160 + aseg*64 + j*16, Asrc + tn*32 + j*4);
            cpa16(st + L_ABYTES2 + brow*80 + bseg*16, Bsrc + tn*32);
        }
        CPA_COMMIT();         // unconditional: keep group accounting uniform

        const int p = t % L_STAGES;
        const float* Af = (const float*)(dyn + p*L_STBYTES);
        const __nv_bfloat16* Bt = (const __nv_bfloat16*)(dyn + p*L_STBYTES + L_ABYTES2);
        const int m0 = warp*16 + gid;
        #pragma unroll
        for (int s=0; s<2; ++s){
            const int c0 = s*16 + tg*2;
            float2 f0 = *(const float2*)&Af[(size_t)m0*40 + c0];
            float2 f1 = *(const float2*)&Af[(size_t)(m0+8)*40 + c0];
            float2 f2 = *(const float2*)&Af[(size_t)m0*40 + c0 + 8];
            float2 f3 = *(const float2*)&Af[(size_t)(m0+8)*40 + c0 + 8];
            uint32_t a0 = cvt2bf(f0.x, f0.y);
            uint32_t a1 = cvt2bf(f1.x, f1.y);
            uint32_t a2 = cvt2bf(f2.x, f2.y);
            uint32_t a3 = cvt2bf(f3.x, f3.y);
            #pragma unroll
            for (int nt=0; nt<8; nt++){
                const int bo = (nt*8 + gid)*40 + s*16 + tg*2;
                uint32_t b0 = *(const uint32_t*)(Bt + bo);
                uint32_t b1 = *(const uint32_t*)(Bt + bo + 8);
                mma16816(acc[nt][0],acc[nt][1],acc[nt][2],acc[nt][3], a0,a1,a2,a3, b0,b1);
            }
        }
    }
    CPA_WAIT(0);
    __syncthreads();   // compute done before aliasing smem

    float* scf = (float*)dyn;   // [64][SC_PITCH]
    const int m0 = warp*16 + gid, m1 = m0 + 8;
    const float bo0 = b_out[vb + m0];
    const float bo1 = b_out[vb + m1];
    #pragma unroll
    for (int nt=0; nt<8; nt++){
        const int n0 = nt*8 + tg*2;
        scf[(size_t)(n0  )*SC_PITCH + m0] = acc[nt][0] + bo0;
        scf[(size_t)(n0+1)*SC_PITCH + m0] = acc[nt][1] + bo0;
        scf[(size_t)(n0  )*SC_PITCH + m1] = acc[nt][2] + bo1;
        scf[(size_t)(n0+1)*SC_PITCH + m1] = acc[nt][3] + bo1;
    }
    __syncthreads();
    const int b = tid>>2, qq = tid&3;
    float* orow = out + (size_t)b*VV + vb;
    #pragma unroll
    for (int i=0;i<8;i++){
        const int f = qq*8 + i;
        *(float4*)&orow[f*4] = *(const float4*)&scf[(size_t)b*SC_PITCH + f*4];
    }
}

// ---------------------------------------------------------------------------
// Kernel 6: in-place log_softmax, float4. 64 blocks x 1024.
// ---------------------------------------------------------------------------
__global__ __launch_bounds__(1024) void logsoftmax_kernel(float* __restrict__ out)
{
    __shared__ float red[33];
    const int b = blockIdx.x, tid = threadIdx.x, lane = tid & 31, warp = tid >> 5;
    float* row = out + (size_t)b*VV;
    float4 vals[8];
    float m = -3.0e38f;
    #pragma unroll
    for (int j=0;j<8;j++){
        int idx = tid*4 + j*4096;
        if (idx < VV){
            vals[j] = *(const float4*)&row[idx];
            m = fmaxf(m, fmaxf(fmaxf(vals[j].x, vals[j].y), fmaxf(vals[j].z, vals[j].w)));
        } else {
            vals[j] = make_float4(-3.0e38f,-3.0e38f,-3.0e38f,-3.0e38f);
        }
    }
    #pragma unroll
    for (int o=16;o;o>>=1) m = fmaxf(m, __shfl_xor_sync(0xffffffffu, m, o));
    if (lane==0) red[warp] = m;
    __syncthreads();
    if (warp==0){
        float v = red[lane];
        #pragma unroll
        for (int o=16;o;o>>=1) v = fmaxf(v, __shfl_xor_sync(0xffffffffu, v, o));
        if (lane==0) red[32] = v;
    }
    __syncthreads();
    m = red[32];
    __syncthreads();
    float z = 0.f;
    #pragma unroll
    for (int j=0;j<8;j++){
        int idx = tid*4 + j*4096;
        if (idx < VV)
            z += __expf(vals[j].x - m) + __expf(vals[j].y - m)
               + __expf(vals[j].z - m) + __expf(vals[j].w - m);
    }
    #pragma unroll
    for (int o=16;o;o>>=1) z += __shfl_xor_sync(0xffffffffu, z, o);
    if (lane==0) red[warp] = z;
    __syncthreads();
    if (warp==0){
        float v = red[lane];
        #pragma unroll
        for (int o=16;o;o>>=1) v += __shfl_xor_sync(0xffffffffu, v, o);
        if (lane==0) red[32] = v;
    }
    __syncthreads();
    const float lse = m + logf(red[32]);
    #pragma unroll
    for (int j=0;j<8;j++){
        int idx = tid*4 + j*4096;
        if (idx < VV){
            float4 o4 = make_float4(vals[j].x - lse, vals[j].y - lse,
                                    vals[j].z - lse, vals[j].w - lse);
            *(float4*)&row[idx] = o4;
        }
    }
}

// ---------------------------------------------------------------------------
extern "C" void kernel_launch(void* const* d_in, const int* in_sizes, int n_in,
                              void* d_out, int out_size)
{
    const int*   input_batch = (const int*)  d_in[0];
    const float* prev_h      = (const float*)d_in[1];
    const float* prev_c      = (const float*)d_in[2];
    const float* enc         = (const float*)d_in[3];
    const int*   lengths     = (const int*)  d_in[4];
    const float* emb         = (const float*)d_in[5];
    const float* attn_w      = (const float*)d_in[6];
    const float* attn_b      = (const float*)d_in[7];
    const float* W_ih        = (const float*)d_in[8];
    const float* W_hh        = (const float*)d_in[9];
    const float* b_ih        = (const float*)d_in[10];
    const float* b_hh        = (const float*)d_in[11];
    const float* W_out       = (const float*)d_in[12];
    const float* b_out       = (const float*)d_in[13];
    float* out = (float*)d_out;

    cudaFuncSetAttribute(logits_gemm_ca, cudaFuncAttributeMaxDynamicSharedMemorySize, L_SMEM);

    scores_kernel<<<dim3(64,4), 256>>>(input_batch, prev_h, enc, emb, attn_w, attn_b);
    ctx_kernel<<<dim3(64,4), 256>>>(enc, out);
    gates_gemm_mma<<<dim3(32, KSPLIT), 256>>>(W_ih, W_hh);
    lstm_kernel<<<256, 256>>>(prev_c, lengths, b_ih, b_hh, out);
    logits_gemm_ca<<<250, 256, L_SMEM>>>(W_out, b_out, out);
    logsoftmax_kernel<<<64, 1024>>>(out);
}

// round 11
// speedup vs baseline: 1.4402x; 1.0111x over previous
#include <cuda_runtime.h>
#include <cuda_bf16.h>
#include <cstdint>
#include <math.h>

// Problem dims
#define BB 64
#define HH 1024
#define SS 128
#define VV 32000
#define KCAT 3072      // E + H + H (emb | context | h0)
#define G4 4096        // 4*H
#define KSPLIT 6

// d_out layout (floats)
#define OUT_H1   (64*32000)
#define OUT_C1   (OUT_H1 + 64*1024)
#define OUT_ATTN (OUT_C1 + 64*1024)

// Scratch (no allocation allowed -> device globals)
__device__ __align__(16) __nv_bfloat16 g_xh[BB*KCAT];  // [b][k] hi: emb|ctx|h0
__device__ __align__(16) __nv_bfloat16 g_xl[BB*KCAT];  // [b][k] lo
__device__ __align__(16) __nv_bfloat16 g_h1bf[BB*HH];  // h1 bf16, [b][k]
__device__ __align__(16) float g_part[KSPLIT*G4*BB];   // gates K-split partials
__device__ __align__(16) float g_scores[BB*SS];        // attention scores
__device__ float g_pmax[BB*4];                          // logsoftmax partial max
__device__ float g_psum[BB*4];                          // logsoftmax partial sumexp
__device__ float g_lse[BB];                             // logsoftmax lse per row

typedef unsigned long long ull;
__device__ __forceinline__ void mma16816(float& c0, float& c1, float& c2, float& c3,
                                         uint32_t a0, uint32_t a1, uint32_t a2, uint32_t a3,
                                         uint32_t b0, uint32_t b1){
    asm("mma.sync.aligned.m16n8k16.row.col.f32.bf16.bf16.f32 "
        "{%0,%1,%2,%3},{%4,%5,%6,%7},{%8,%9},{%0,%1,%2,%3};"
        : "+f"(c0), "+f"(c1), "+f"(c2), "+f"(c3)
        : "r"(a0), "r"(a1), "r"(a2), "r"(a3), "r"(b0), "r"(b1));
}
__device__ __forceinline__ uint32_t cvt2bf(float lo, float hi){
    __nv_bfloat162 h = __floats2bfloat162_rn(lo, hi);   // .x = lo
    return *(uint32_t*)&h;
}
__device__ __forceinline__ void split2(float x, float y, uint32_t& hi, uint32_t& lo){
    __nv_bfloat162 h = __floats2bfloat162_rn(x, y);
    float rx = x - __bfloat162float(h.x);
    float ry = y - __bfloat162float(h.y);
    __nv_bfloat162 l = __floats2bfloat162_rn(rx, ry);
    hi = *(uint32_t*)&h; lo = *(uint32_t*)&l;
}
__device__ __forceinline__ void splitbf(float x, __nv_bfloat16* ph, __nv_bfloat16* pl){
    __nv_bfloat16 h = __float2bfloat16(x);
    *ph = h;
    *pl = __float2bfloat16(x - __bfloat162float(h));
}
__device__ __forceinline__ void cpa16(uint32_t dst, const void* src){
    asm volatile("cp.async.cg.shared.global [%0], [%1], 16;" :: "r"(dst), "l"(src));
}
#define CPA_COMMIT() asm volatile("cp.async.commit_group;" ::: "memory")
#define CPA_WAIT(n)  asm volatile("cp.async.wait_group %0;" :: "n"(n) : "memory")

// ---------------------------------------------------------------------------
// Kernel 1: scores + emb/h0 bf16 prep. grid (64, 4), 256 thr. (unchanged)
// ---------------------------------------------------------------------------
__global__ void scores_kernel(const int* __restrict__ input_batch, const float* __restrict__ prev_h,
                              const float* __restrict__ enc, const float* __restrict__ emb,
                              const float* __restrict__ attn_w, const float* __restrict__ attn_b)
{
    __shared__ float sw2[1024];
    __shared__ float red[40];
    const int b = blockIdx.x, q = blockIdx.y;
    const int tid = threadIdx.x, lane = tid & 31, warp = tid >> 5;
    const int tok = input_batch[b];
    __nv_bfloat16* xh = g_xh + (size_t)b*KCAT;
    __nv_bfloat16* xl = g_xl + (size_t)b*KCAT;

    float hacc = 0.f;
    #pragma unroll
    for (int k = 0; k < 4; k++){
        const int i = tid + k*256;
        float h0v = prev_h[(size_t)b*1024 + i];
        hacc += attn_w[i] * h0v;
        sw2[i] = attn_w[1024 + i];
        if (k == q){
            splitbf(h0v, xh + 2048 + i, xl + 2048 + i);
            float xe = emb[(size_t)tok*1024 + i];
            splitbf(xe, xh + i, xl + i);
        }
    }
    #pragma unroll
    for (int o=16;o;o>>=1) hacc += __shfl_xor_sync(0xffffffffu, hacc, o);
    if (lane==0) red[warp] = hacc;
    __syncthreads();
    if (tid==0){ float s=0.f; for (int w=0;w<8;w++) s+=red[w]; red[32] = s + attn_b[0]; }
    __syncthreads();
    const float hpb = red[32];

    const float* encb = enc + (size_t)b*SS*HH;
    #pragma unroll
    for (int s4 = 0; s4 < 4; s4++){
        const int s = q*32 + warp*4 + s4;
        const float* ep = encb + (size_t)s*1024;
        float acc = 0.f;
        #pragma unroll 8
        for (int j=0;j<32;j++){ int i = lane + j*32; acc += ep[i]*sw2[i]; }
        #pragma unroll
        for (int o=16;o;o>>=1) acc += __shfl_xor_sync(0xffffffffu, acc, o);
        if (lane==0) g_scores[b*128 + s] = acc + hpb;
    }
}

// ---------------------------------------------------------------------------
// Kernel 2: softmax + context slice. grid (64, 4), 256 thr. (unchanged)
// ---------------------------------------------------------------------------
__global__ void ctx_kernel(const float* __restrict__ enc, float* __restrict__ out)
{
    __shared__ float sweights[128];
    __shared__ float red[40];
    const int b = blockIdx.x, hc = blockIdx.y;
    const int tid = threadIdx.x, lane = tid & 31, warp = tid >> 5;

    float sc = (tid<128) ? g_scores[b*128 + tid] : -3.0e38f;
    float m = sc;
    #pragma unroll
    for (int o=16;o;o>>=1) m = fmaxf(m, __shfl_xor_sync(0xffffffffu, m, o));
    if (lane==0) red[warp] = m;
    __syncthreads();
    if (tid==0){ float mm=red[0]; for (int w=1;w<8;w++) mm=fmaxf(mm,red[w]); red[33]=mm; }
    __syncthreads();
    m = red[33];
    float e = (tid<128) ? __expf(sc - m) : 0.f;
    float z = e;
    #pragma unroll
    for (int o=16;o;o>>=1) z += __shfl_xor_sync(0xffffffffu, z, o);
    if (lane==0) red[warp] = z;
    __syncthreads();
    if (tid==0){ float s=0.f; for (int w=0;w<8;w++) s+=red[w]; red[34]=s; }
    __syncthreads();
    const float Z = red[34];
    if (tid < 128){
        float w = e / Z;
        sweights[tid] = w;
        if (hc == 0) out[OUT_ATTN + b*128 + tid] = w;
    }
    __syncthreads();

    const int h = hc*256 + tid;
    const float* ecol = enc + (size_t)b*SS*HH + h;
    float acc = 0.f;
    #pragma unroll 4
    for (int s=0; s<128; s++) acc += sweights[s] * ecol[(size_t)s*1024];
    splitbf(acc, g_xh + (size_t)b*KCAT + 1024 + h, g_xl + (size_t)b*KCAT + 1024 + h);
}

// ---------------------------------------------------------------------------
// Kernel 3: gates GEMM, cp.async 3-stage pipeline (clone of logits structure).
// A fp32 staged (128 x 32 per chunk, pitch 40 fl), split to hi/lo bf16 in regs.
// B hi/lo bf16 staged. 3 MMAs per fragment (hh + hl + lh). grid (32,6), 256 thr.
// ---------------------------------------------------------------------------
#define GS_STAGES 3
#define GS_AB 20480                 // A: 128 rows * 160B (pitch 40 floats)
#define GS_BHOFF 20480              // Bh at +20480 (64 x 80B)
#define GS_BLOFF 25600              // Bl at +25600 (64 x 80B)
#define GS_ST 30720                 // stage bytes
#define GS_SMEM 92160               // 3 stages

extern "C" __global__ __launch_bounds__(256) void gates_gemm_ca(
    const float* __restrict__ W_ih, const float* __restrict__ W_hh)
{
    extern __shared__ __align__(16) unsigned char dyn[];
    const int tid = threadIdx.x, lane = tid & 31, warp = tid >> 5;
    const int gid = lane >> 2, tg = lane & 3;
    const int g0 = blockIdx.x * 128;
    const int ky = blockIdx.y;
    const bool ih = (ky < 4);
    const uint32_t smb = (uint32_t)__cvta_generic_to_shared(dyn);

    const int arow = tid >> 1, aseg = tid & 1;     // A: 2 thr/row, 64B each
    const int brow = tid >> 2, bseg = tid & 3;     // B: 4 thr/row, 16B each
    const float* Asrc = ih ? (W_ih + (size_t)(g0 + arow)*2048 + ky*512 + aseg*16)
                           : (W_hh + (size_t)(g0 + arow)*1024 + (ky-4)*512 + aseg*16);
    const int kb = ky*512;
    const __nv_bfloat16* Bsh = g_xh + (size_t)brow*KCAT + kb + bseg*8;
    const __nv_bfloat16* Bsl = g_xl + (size_t)brow*KCAT + kb + bseg*8;

    const int NCH = 512/32;   // 16

    #pragma unroll
    for (int t=0; t<GS_STAGES-1; ++t){
        const uint32_t st = smb + t*GS_ST;
        #pragma unroll
        for (int j=0;j<4;j++)
            cpa16(st + arow*160 + aseg*64 + j*16, Asrc + t*32 + j*4);
        cpa16(st + GS_BHOFF + brow*80 + bseg*16, Bsh + t*32);
        cpa16(st + GS_BLOFF + brow*80 + bseg*16, Bsl + t*32);
        CPA_COMMIT();
    }

    float acc[8][4];
    #pragma unroll
    for (int nt=0; nt<8; nt++){ acc[nt][0]=0.f; acc[nt][1]=0.f; acc[nt][2]=0.f; acc[nt][3]=0.f; }

    for (int t=0; t<NCH; ++t){
        CPA_WAIT(1);
        __syncthreads();
        if (t + GS_STAGES - 1 < NCH){
            const int tn = t + GS_STAGES - 1;
            const uint32_t st = smb + (tn % GS_STAGES)*GS_ST;
            #pragma unroll
            for (int j=0;j<4;j++)
                cpa16(st + arow*160 + aseg*64 + j*16, Asrc + tn*32 + j*4);
            cpa16(st + GS_BHOFF + brow*80 + bseg*16, Bsh + tn*32);
            cpa16(st + GS_BLOFF + brow*80 + bseg*16, Bsl + tn*32);
        }
        CPA_COMMIT();

        const int p = t % GS_STAGES;
        const float* Af = (const float*)(dyn + p*GS_ST);
        const __nv_bfloat16* Bth = (const __nv_bfloat16*)(dyn + p*GS_ST + GS_BHOFF);
        const __nv_bfloat16* Btl = (const __nv_bfloat16*)(dyn + p*GS_ST + GS_BLOFF);
        const int m0 = warp*16 + gid;
        #pragma unroll
        for (int s=0; s<2; ++s){
            const int c0 = s*16 + tg*2;
            float2 f0 = *(const float2*)&Af[(size_t)m0*40 + c0];
            float2 f1 = *(const float2*)&Af[(size_t)(m0+8)*40 + c0];
            float2 f2 = *(const float2*)&Af[(size_t)m0*40 + c0 + 8];
            float2 f3 = *(const float2*)&Af[(size_t)(m0+8)*40 + c0 + 8];
            uint32_t ah0,al0, ah1,al1, ah2,al2, ah3,al3;
            split2(f0.x, f0.y, ah0, al0);
            split2(f1.x, f1.y, ah1, al1);
            split2(f2.x, f2.y, ah2, al2);
            split2(f3.x, f3.y, ah3, al3);
            #pragma unroll
            for (int nt=0; nt<8; nt++){
                const int bo = (nt*8 + gid)*40 + s*16 + tg*2;
                uint32_t bh0 = *(const uint32_t*)(Bth + bo);
                uint32_t bh1 = *(const uint32_t*)(Bth + bo + 8);
                uint32_t bl0 = *(const uint32_t*)(Btl + bo);
                uint32_t bl1 = *(const uint32_t*)(Btl + bo + 8);
                mma16816(acc[nt][0],acc[nt][1],acc[nt][2],acc[nt][3], ah0,ah1,ah2,ah3, bh0,bh1);
                mma16816(acc[nt][0],acc[nt][1],acc[nt][2],acc[nt][3], ah0,ah1,ah2,ah3, bl0,bl1);
                mma16816(acc[nt][0],acc[nt][1],acc[nt][2],acc[nt][3], al0,al1,al2,al3, bh0,bh1);
            }
        }
    }
    CPA_WAIT(0);

    float* P = g_part + (size_t)ky*G4*64;
    const int m0 = g0 + warp*16 + gid, m1 = m0 + 8;
    #pragma unroll
    for (int nt=0; nt<8; nt++){
        const int n0 = nt*8 + tg*2;
        *(float2*)&P[(size_t)m0*64 + n0] = make_float2(acc[nt][0], acc[nt][1]);
        *(float2*)&P[(size_t)m1*64 + n0] = make_float2(acc[nt][2], acc[nt][3]);
    }
}

// ---------------------------------------------------------------------------
// Kernel 4: K-split reduce + biases + LSTM cell (unchanged)
// ---------------------------------------------------------------------------
__global__ void lstm_kernel(const float* __restrict__ prev_c, const int* __restrict__ lengths,
                            const float* __restrict__ b_ih, const float* __restrict__ b_hh,
                            float* __restrict__ out)
{
    const int id = blockIdx.x*256 + threadIdx.x;
    const int b = id & 63, h = id >> 6;
    float s[4] = {0.f,0.f,0.f,0.f};
    #pragma unroll
    for (int ky=0; ky<KSPLIT; ++ky){
        const float* P = g_part + (size_t)ky*G4*64;
        #pragma unroll
        for (int g=0; g<4; ++g) s[g] += P[(size_t)(g*1024 + h)*64 + b];
    }
    #pragma unroll
    for (int g=0; g<4; ++g) s[g] += b_ih[g*1024+h] + b_hh[g*1024+h];
    float ig = 1.f/(1.f + __expf(-s[0]));
    float fg = 1.f/(1.f + __expf(-s[1]));
    float gg = tanhf(s[2]);
    float og = 1.f/(1.f + __expf(-s[3]));
    float c0 = prev_c[(size_t)b*HH + h];
    float c1 = fg*c0 + ig*gg;
    float h1 = og*tanhf(c1);
    if (lengths[b] == 0){ c1 = 0.f; h1 = 0.f; }
    out[OUT_H1 + b*HH + h] = h1;
    out[OUT_C1 + b*HH + h] = c1;
    g_h1bf[(size_t)b*HH + h] = __float2bfloat16(h1);
}

// ---------------------------------------------------------------------------
// Kernel 5: logits GEMM, cp.async 3-stage pipeline (unchanged; proven)
// ---------------------------------------------------------------------------
#define L_STAGES 3
#define L_ABYTES2 20480
#define L_STBYTES 25600
#define SC_PITCH 132
#define L_SMEM 76800

extern "C" __global__ __launch_bounds__(256) void logits_gemm_ca(
    const float* __restrict__ W_out, const float* __restrict__ b_out, float* __restrict__ out)
{
    extern __shared__ __align__(16) unsigned char dyn[];
    const int tid = threadIdx.x, lane = tid & 31, warp = tid >> 5;
    const int gid = lane >> 2, tg = lane & 3;
    const int vb = blockIdx.x * 128;
    const uint32_t smb = (uint32_t)__cvta_generic_to_shared(dyn);

    const int arow = tid >> 1, aseg = tid & 1;
    const int brow = tid >> 2, bseg = tid & 3;
    const float* Asrc = W_out + (size_t)(vb + arow)*HH + aseg*16;
    const __nv_bfloat16* Bsrc = g_h1bf + (size_t)brow*HH + bseg*8;

    const int NCH = HH/32;   // 32

    #pragma unroll
    for (int t=0; t<L_STAGES-1; ++t){
        const uint32_t st = smb + t*L_STBYTES;
        #pragma unroll
        for (int j=0;j<4;j++)
            cpa16(st + arow*160 + aseg*64 + j*16, Asrc + t*32 + j*4);
        cpa16(st + L_ABYTES2 + brow*80 + bseg*16, Bsrc + t*32);
        CPA_COMMIT();
    }

    float acc[8][4];
    #pragma unroll
    for (int nt=0; nt<8; nt++){ acc[nt][0]=0.f; acc[nt][1]=0.f; acc[nt][2]=0.f; acc[nt][3]=0.f; }

    for (int t=0; t<NCH; ++t){
        CPA_WAIT(1);
        __syncthreads();
        if (t + L_STAGES - 1 < NCH){
            const int tn = t + L_STAGES - 1;
            const uint32_t st = smb + (tn % L_STAGES)*L_STBYTES;
            #pragma unroll
            for (int j=0;j<4;j++)
                cpa16(st + arow*160 + aseg*64 + j*16, Asrc + tn*32 + j*4);
            cpa16(st + L_ABYTES2 + brow*80 + bseg*16, Bsrc + tn*32);
        }
        CPA_COMMIT();

        const int p = t % L_STAGES;
        const float* Af = (const float*)(dyn + p*L_STBYTES);
        const __nv_bfloat16* Bt = (const __nv_bfloat16*)(dyn + p*L_STBYTES + L_ABYTES2);
        const int m0 = warp*16 + gid;
        #pragma unroll
        for (int s=0; s<2; ++s){
            const int c0 = s*16 + tg*2;
            float2 f0 = *(const float2*)&Af[(size_t)m0*40 + c0];
            float2 f1 = *(const float2*)&Af[(size_t)(m0+8)*40 + c0];
            float2 f2 = *(const float2*)&Af[(size_t)m0*40 + c0 + 8];
            float2 f3 = *(const float2*)&Af[(size_t)(m0+8)*40 + c0 + 8];
            uint32_t a0 = cvt2bf(f0.x, f0.y);
            uint32_t a1 = cvt2bf(f1.x, f1.y);
            uint32_t a2 = cvt2bf(f2.x, f2.y);
            uint32_t a3 = cvt2bf(f3.x, f3.y);
            #pragma unroll
            for (int nt=0; nt<8; nt++){
                const int bo = (nt*8 + gid)*40 + s*16 + tg*2;
                uint32_t b0 = *(const uint32_t*)(Bt + bo);
                uint32_t b1 = *(const uint32_t*)(Bt + bo + 8);
                mma16816(acc[nt][0],acc[nt][1],acc[nt][2],acc[nt][3], a0,a1,a2,a3, b0,b1);
            }
        }
    }
    CPA_WAIT(0);
    __syncthreads();

    float* scf = (float*)dyn;
    const int m0 = warp*16 + gid, m1 = m0 + 8;
    const float bo0 = b_out[vb + m0];
    const float bo1 = b_out[vb + m1];
    #pragma unroll
    for (int nt=0; nt<8; nt++){
        const int n0 = nt*8 + tg*2;
        scf[(size_t)(n0  )*SC_PITCH + m0] = acc[nt][0] + bo0;
        scf[(size_t)(n0+1)*SC_PITCH + m0] = acc[nt][1] + bo0;
        scf[(size_t)(n0  )*SC_PITCH + m1] = acc[nt][2] + bo1;
        scf[(size_t)(n0+1)*SC_PITCH + m1] = acc[nt][3] + bo1;
    }
    __syncthreads();
    const int b = tid>>2, qq = tid&3;
    float* orow = out + (size_t)b*VV + vb;
    #pragma unroll
    for (int i=0;i<8;i++){
        const int f = qq*8 + i;
        *(float4*)&orow[f*4] = *(const float4*)&scf[(size_t)b*SC_PITCH + f*4];
    }
}

// ---------------------------------------------------------------------------
// Kernel 6a: logsoftmax partials. grid (64,4), 1024 thr. 8000 cols per block.
// ---------------------------------------------------------------------------
__global__ __launch_bounds__(1024) void ls_partial(const float* __restrict__ out)
{
    __shared__ float red[33];
    const int b = blockIdx.x, q = blockIdx.y;
    const int tid = threadIdx.x, lane = tid & 31, warp = tid >> 5;
    const float* row = out + (size_t)b*VV + q*8000;
    float4 vals[2];
    float m = -3.0e38f;
    #pragma unroll
    for (int j=0;j<2;j++){
        const int i4 = tid + j*1024;       // 2000 float4 per block
        if (i4 < 2000){
            vals[j] = *(const float4*)&row[i4*4];
            m = fmaxf(m, fmaxf(fmaxf(vals[j].x, vals[j].y), fmaxf(vals[j].z, vals[j].w)));
        } else vals[j] = make_float4(-3.0e38f,-3.0e38f,-3.0e38f,-3.0e38f);
    }
    #pragma unroll
    for (int o=16;o;o>>=1) m = fmaxf(m, __shfl_xor_sync(0xffffffffu, m, o));
    if (lane==0) red[warp] = m;
    __syncthreads();
    if (warp==0){
        float v = red[lane];
        #pragma unroll
        for (int o=16;o;o>>=1) v = fmaxf(v, __shfl_xor_sync(0xffffffffu, v, o));
        if (lane==0) red[32] = v;
    }
    __syncthreads();
    m = red[32];
    __syncthreads();
    float z = 0.f;
    #pragma unroll
    for (int j=0;j<2;j++){
        const int i4 = tid + j*1024;
        if (i4 < 2000)
            z += __expf(vals[j].x - m) + __expf(vals[j].y - m)
               + __expf(vals[j].z - m) + __expf(vals[j].w - m);
    }
    #pragma unroll
    for (int o=16;o;o>>=1) z += __shfl_xor_sync(0xffffffffu, z, o);
    if (lane==0) red[warp] = z;
    __syncthreads();
    if (warp==0){
        float v = red[lane];
        #pragma unroll
        for (int o=16;o;o>>=1) v += __shfl_xor_sync(0xffffffffu, v, o);
        if (lane==0){ g_pmax[b*4+q] = m; g_psum[b*4+q] = v; }
    }
}

// ---------------------------------------------------------------------------
// Kernel 6b: combine partials -> lse[64]. 1 block, 64 threads.
// ---------------------------------------------------------------------------
__global__ void ls_combine()
{
    const int b = threadIdx.x;
    float m = g_pmax[b*4];
    #pragma unroll
    for (int q=1;q<4;q++) m = fmaxf(m, g_pmax[b*4+q]);
    float s = 0.f;
    #pragma unroll
    for (int q=0;q<4;q++) s += g_psum[b*4+q] * __expf(g_pmax[b*4+q] - m);
    g_lse[b] = m + logf(s);
}

// ---------------------------------------------------------------------------
// Kernel 6c: subtract lse. grid (64,4), 1024 thr.
// ---------------------------------------------------------------------------
__global__ __launch_bounds__(1024) void ls_norm(float* __restrict__ out)
{
    const int b = blockIdx.x, q = blockIdx.y;
    const int tid = threadIdx.x;
    const float lse = g_lse[b];
    float* row = out + (size_t)b*VV + q*8000;
    #pragma unroll
    for (int j=0;j<2;j++){
        const int i4 = tid + j*1024;
        if (i4 < 2000){
            float4 v = *(const float4*)&row[i4*4];
            v.x -= lse; v.y -= lse; v.z -= lse; v.w -= lse;
            *(float4*)&row[i4*4] = v;
        }
    }
}

// ---------------------------------------------------------------------------
extern "C" void kernel_launch(void* const* d_in, const int* in_sizes, int n_in,
                              void* d_out, int out_size)
{
    const int*   input_batch = (const int*)  d_in[0];
    const float* prev_h      = (const float*)d_in[1];
    const float* prev_c      = (const float*)d_in[2];
    const float* enc         = (const float*)d_in[3];
    const int*   lengths     = (const int*)  d_in[4];
    const float* emb         = (const float*)d_in[5];
    const float* attn_w      = (const float*)d_in[6];
    const float* attn_b      = (const float*)d_in[7];
    const float* W_ih        = (const float*)d_in[8];
    const float* W_hh        = (const float*)d_in[9];
    const float* b_ih        = (const float*)d_in[10];
    const float* b_hh        = (const float*)d_in[11];
    const float* W_out       = (const float*)d_in[12];
    const float* b_out       = (const float*)d_in[13];
    float* out = (float*)d_out;

    cudaFuncSetAttribute(logits_gemm_ca, cudaFuncAttributeMaxDynamicSharedMemorySize, L_SMEM);
    cudaFuncSetAttribute(gates_gemm_ca,  cudaFuncAttributeMaxDynamicSharedMemorySize, GS_SMEM);

    scores_kernel<<<dim3(64,4), 256>>>(input_batch, prev_h, enc, emb, attn_w, attn_b);
    ctx_kernel<<<dim3(64,4), 256>>>(enc, out);
    gates_gemm_ca<<<dim3(32, KSPLIT), 256, GS_SMEM>>>(W_ih, W_hh);
    lstm_kernel<<<256, 256>>>(prev_c, lengths, b_ih, b_hh, out);
    logits_gemm_ca<<<250, 256, L_SMEM>>>(W_out, b_out, out);
    ls_partial<<<dim3(64,4), 1024>>>(out);
    ls_combine<<<1, 64>>>();
    ls_norm<<<dim3(64,4), 1024>>>(out);
}

// round 14
// speedup vs baseline: 1.6173x; 1.1230x over previous
#include <cuda_runtime.h>
#include <cuda_bf16.h>
#include <cstdint>
#include <math.h>

// Problem dims
#define BB 64
#define HH 1024
#define SS 128
#define VV 32000
#define KCAT 3072      // E + H + H (emb | context | h0)
#define G4 4096        // 4*H
#define KSPLIT 6

// d_out layout (floats)
#define OUT_H1   (64*32000)
#define OUT_C1   (OUT_H1 + 64*1024)
#define OUT_ATTN (OUT_C1 + 64*1024)

// Scratch (no allocation allowed -> device globals)
__device__ __align__(16) __nv_bfloat16 g_xh[BB*KCAT];  // [b][k] hi: emb|ctx|h0
__device__ __align__(16) __nv_bfloat16 g_xl[BB*KCAT];  // [b][k] lo
__device__ __align__(16) __nv_bfloat16 g_h1bf[BB*HH];  // h1 bf16, [b][k]
__device__ __align__(16) float g_part[KSPLIT*G4*BB];   // gates K-split partials
__device__ __align__(16) float g_scores[BB*SS];        // attention raw scores
__device__ __align__(16) float g_actx[BB*4*HH];        // attn partial context
__device__ float g_am[BB*4];                            // attn partial max
__device__ float g_aZ[BB*4];                            // attn partial Z
__device__ float g_pmax[BB*4];                          // logsoftmax partial max
__device__ float g_psum[BB*4];                          // logsoftmax partial sumexp

typedef unsigned long long ull;
__device__ __forceinline__ void mma16816(float& c0, float& c1, float& c2, float& c3,
                                         uint32_t a0, uint32_t a1, uint32_t a2, uint32_t a3,
                                         uint32_t b0, uint32_t b1){
    asm("mma.sync.aligned.m16n8k16.row.col.f32.bf16.bf16.f32 "
        "{%0,%1,%2,%3},{%4,%5,%6,%7},{%8,%9},{%0,%1,%2,%3};"
        : "+f"(c0), "+f"(c1), "+f"(c2), "+f"(c3)
        : "r"(a0), "r"(a1), "r"(a2), "r"(a3), "r"(b0), "r"(b1));
}
__device__ __forceinline__ uint32_t cvt2bf(float lo, float hi){
    __nv_bfloat162 h = __floats2bfloat162_rn(lo, hi);   // .x = lo
    return *(uint32_t*)&h;
}
__device__ __forceinline__ void split2(float x, float y, uint32_t& hi, uint32_t& lo){
    __nv_bfloat162 h = __floats2bfloat162_rn(x, y);
    float rx = x - __bfloat162float(h.x);
    float ry = y - __bfloat162float(h.y);
    __nv_bfloat162 l = __floats2bfloat162_rn(rx, ry);
    hi = *(uint32_t*)&h; lo = *(uint32_t*)&l;
}
__device__ __forceinline__ void splitbf(float x, __nv_bfloat16* ph, __nv_bfloat16* pl){
    __nv_bfloat16 h = __float2bfloat16(x);
    *ph = h;
    *pl = __float2bfloat16(x - __bfloat162float(h));
}
__device__ __forceinline__ void cpa16(uint32_t dst, const void* src){
    asm volatile("cp.async.cg.shared.global [%0], [%1], 16;" :: "r"(dst), "l"(src));
}
#define CPA_COMMIT() asm volatile("cp.async.commit_group;" ::: "memory")
#define CPA_WAIT(n)  asm volatile("cp.async.wait_group %0;" :: "n"(n) : "memory")

// ---------------------------------------------------------------------------
// Kernel 1: fused flash-style attention partial. grid (64,4), 256 thr.
// Block (b,q): rows s in [q*32,(q+1)*32), 4 rows/warp, single pass over enc.
// Per-warp online softmax (m, Z, ctx[32] regs), block-combine into partials.
// ---------------------------------------------------------------------------
__global__ __launch_bounds__(256) void attn_partial(const float* __restrict__ prev_h,
                                                    const float* __restrict__ enc,
                                                    const float* __restrict__ attn_w,
                                                    const float* __restrict__ attn_b)
{
    __shared__ float sw2[1024];
    __shared__ float red[40];
    __shared__ float s_m[8], s_Z[8];
    __shared__ float s_ctx[8][1024];
    const int b = blockIdx.x, q = blockIdx.y;
    const int tid = threadIdx.x, lane = tid & 31, warp = tid >> 5;

    // h_part + load w2 (redundant across q; 12KB)
    float hacc = 0.f;
    #pragma unroll
    for (int k = 0; k < 4; k++){
        const int i = tid + k*256;
        hacc += attn_w[i] * prev_h[(size_t)b*1024 + i];
        sw2[i] = attn_w[1024 + i];
    }
    #pragma unroll
    for (int o=16;o;o>>=1) hacc += __shfl_xor_sync(0xffffffffu, hacc, o);
    if (lane==0) red[warp] = hacc;
    __syncthreads();
    if (tid==0){ float s=0.f; for (int w=0;w<8;w++) s+=red[w]; red[32] = s + attn_b[0]; }
    __syncthreads();
    const float hpb = red[32];

    // per-warp single pass over 4 rows: score + online softmax context
    const float* encb = enc + (size_t)b*SS*HH;
    float m = -3.0e38f, Z = 0.f;
    float ctx[32];
    #pragma unroll
    for (int j=0;j<32;j++) ctx[j] = 0.f;

    #pragma unroll
    for (int r=0;r<4;r++){
        const int s = q*32 + warp*4 + r;
        const float* ep = encb + (size_t)s*1024;
        float row[32];
        float dot = 0.f;
        #pragma unroll
        for (int j=0;j<32;j++){
            row[j] = ep[lane + j*32];           // dim = j*32 + lane
            dot += row[j]*sw2[lane + j*32];
        }
        #pragma unroll
        for (int o=16;o;o>>=1) dot += __shfl_xor_sync(0xffffffffu, dot, o);
        const float sc = dot + hpb;
        if (lane==0) g_scores[b*128 + s] = sc;
        const float mn = fmaxf(m, sc);
        const float scale = __expf(m - mn);     // m=-3e38 first: 0
        const float c = __expf(sc - mn);
        Z = Z*scale + c;
        #pragma unroll
        for (int j=0;j<32;j++) ctx[j] = ctx[j]*scale + c*row[j];
        m = mn;
    }
    // block combine across 8 warps
    if (lane==0){ s_m[warp] = m; s_Z[warp] = Z; }
    #pragma unroll
    for (int j=0;j<32;j++) s_ctx[warp][j*32 + lane] = ctx[j];
    __syncthreads();

    float mb = s_m[0];
    #pragma unroll
    for (int w=1;w<8;w++) mb = fmaxf(mb, s_m[w]);
    if (tid < 8) red[tid] = s_Z[tid]*__expf(s_m[tid] - mb);
    __syncthreads();
    if (tid==0){ float z=0.f; for (int w=0;w<8;w++) z+=red[w]; red[32]=z; }
    __syncthreads();
    const float Zb = red[32];

    float* cp = g_actx + (size_t)(b*4 + q)*1024;
    #pragma unroll
    for (int k=0;k<4;k++){
        const int i = tid + k*256;
        float acc = 0.f;
        #pragma unroll
        for (int w=0;w<8;w++) acc += s_ctx[w][i]*__expf(s_m[w] - mb);
        cp[i] = acc;
    }
    if (tid==0){ g_am[b*4+q] = mb; g_aZ[b*4+q] = Zb; }
}

// ---------------------------------------------------------------------------
// Kernel 2: attention combine + bf16 prep. grid 64, 256 thr.
// Merges 4 partials; writes attn weights, context/emb/h0 hi-lo splits.
// ---------------------------------------------------------------------------
__global__ __launch_bounds__(256) void attn_combine(const int* __restrict__ input_batch,
                                                    const float* __restrict__ prev_h,
                                                    const float* __restrict__ emb,
                                                    float* __restrict__ out)
{
    const int b = blockIdx.x, tid = threadIdx.x;
    const int tok = input_batch[b];
    __nv_bfloat16* xh = g_xh + (size_t)b*KCAT;
    __nv_bfloat16* xl = g_xl + (size_t)b*KCAT;

    float m = g_am[b*4];
    #pragma unroll
    for (int q=1;q<4;q++) m = fmaxf(m, g_am[b*4+q]);
    float e0 = __expf(g_am[b*4+0] - m);
    float e1 = __expf(g_am[b*4+1] - m);
    float e2 = __expf(g_am[b*4+2] - m);
    float e3 = __expf(g_am[b*4+3] - m);
    const float Z = g_aZ[b*4+0]*e0 + g_aZ[b*4+1]*e1 + g_aZ[b*4+2]*e2 + g_aZ[b*4+3]*e3;
    const float invZ = 1.f/Z;

    if (tid < 128)
        out[OUT_ATTN + b*128 + tid] = __expf(g_scores[b*128 + tid] - m)*invZ;

    const float* cp = g_actx + (size_t)b*4*1024;
    #pragma unroll
    for (int k=0;k<4;k++){
        const int i = tid + k*256;
        float c = (cp[i]*e0 + cp[1024+i]*e1 + cp[2048+i]*e2 + cp[3072+i]*e3)*invZ;
        splitbf(c, xh + 1024 + i, xl + 1024 + i);
        splitbf(prev_h[(size_t)b*1024 + i], xh + 2048 + i, xl + 2048 + i);
        splitbf(emb[(size_t)tok*1024 + i], xh + i, xl + i);
    }
}

// ---------------------------------------------------------------------------
// Kernel 3: gates GEMM, cp.async 3-stage pipeline (unchanged; proven)
// ---------------------------------------------------------------------------
#define GS_STAGES 3
#define GS_BHOFF 20480
#define GS_BLOFF 25600
#define GS_ST 30720
#define GS_SMEM 92160

extern "C" __global__ __launch_bounds__(256) void gates_gemm_ca(
    const float* __restrict__ W_ih, const float* __restrict__ W_hh)
{
    extern __shared__ __align__(16) unsigned char dyn[];
    const int tid = threadIdx.x, lane = tid & 31, warp = tid >> 5;
    const int gid = lane >> 2, tg = lane & 3;
    const int g0 = blockIdx.x * 128;
    const int ky = blockIdx.y;
    const bool ih = (ky < 4);
    const uint32_t smb = (uint32_t)__cvta_generic_to_shared(dyn);

    const int arow = tid >> 1, aseg = tid & 1;
    const int brow = tid >> 2, bseg = tid & 3;
    const float* Asrc = ih ? (W_ih + (size_t)(g0 + arow)*2048 + ky*512 + aseg*16)
                           : (W_hh + (size_t)(g0 + arow)*1024 + (ky-4)*512 + aseg*16);
    const int kb = ky*512;
    const __nv_bfloat16* Bsh = g_xh + (size_t)brow*KCAT + kb + bseg*8;
    const __nv_bfloat16* Bsl = g_xl + (size_t)brow*KCAT + kb + bseg*8;

    const int NCH = 512/32;   // 16

    #pragma unroll
    for (int t=0; t<GS_STAGES-1; ++t){
        const uint32_t st = smb + t*GS_ST;
        #pragma unroll
        for (int j=0;j<4;j++)
            cpa16(st + arow*160 + aseg*64 + j*16, Asrc + t*32 + j*4);
        cpa16(st + GS_BHOFF + brow*80 + bseg*16, Bsh + t*32);
        cpa16(st + GS_BLOFF + brow*80 + bseg*16, Bsl + t*32);
        CPA_COMMIT();
    }

    float acc[8][4];
    #pragma unroll
    for (int nt=0; nt<8; nt++){ acc[nt][0]=0.f; acc[nt][1]=0.f; acc[nt][2]=0.f; acc[nt][3]=0.f; }

    for (int t=0; t<NCH; ++t){
        CPA_WAIT(1);
        __syncthreads();
        if (t + GS_STAGES - 1 < NCH){
            const int tn = t + GS_STAGES - 1;
            const uint32_t st = smb + (tn % GS_STAGES)*GS_ST;
            #pragma unroll
            for (int j=0;j<4;j++)
                cpa16(st + arow*160 + aseg*64 + j*16, Asrc + tn*32 + j*4);
            cpa16(st + GS_BHOFF + brow*80 + bseg*16, Bsh + tn*32);
            cpa16(st + GS_BLOFF + brow*80 + bseg*16, Bsl + tn*32);
        }
        CPA_COMMIT();

        const int p = t % GS_STAGES;
        const float* Af = (const float*)(dyn + p*GS_ST);
        const __nv_bfloat16* Bth = (const __nv_bfloat16*)(dyn + p*GS_ST + GS_BHOFF);
        const __nv_bfloat16* Btl = (const __nv_bfloat16*)(dyn + p*GS_ST + GS_BLOFF);
        const int m0 = warp*16 + gid;
        #pragma unroll
        for (int s=0; s<2; ++s){
            const int c0 = s*16 + tg*2;
            float2 f0 = *(const float2*)&Af[(size_t)m0*40 + c0];
            float2 f1 = *(const float2*)&Af[(size_t)(m0+8)*40 + c0];
            float2 f2 = *(const float2*)&Af[(size_t)m0*40 + c0 + 8];
            float2 f3 = *(const float2*)&Af[(size_t)(m0+8)*40 + c0 + 8];
            uint32_t ah0,al0, ah1,al1, ah2,al2, ah3,al3;
            split2(f0.x, f0.y, ah0, al0);
            split2(f1.x, f1.y, ah1, al1);
            split2(f2.x, f2.y, ah2, al2);
            split2(f3.x, f3.y, ah3, al3);
            #pragma unroll
            for (int nt=0; nt<8; nt++){
                const int bo = (nt*8 + gid)*40 + s*16 + tg*2;
                uint32_t bh0 = *(const uint32_t*)(Bth + bo);
                uint32_t bh1 = *(const uint32_t*)(Bth + bo + 8);
                uint32_t bl0 = *(const uint32_t*)(Btl + bo);
                uint32_t bl1 = *(const uint32_t*)(Btl + bo + 8);
                mma16816(acc[nt][0],acc[nt][1],acc[nt][2],acc[nt][3], ah0,ah1,ah2,ah3, bh0,bh1);
                mma16816(acc[nt][0],acc[nt][1],acc[nt][2],acc[nt][3], ah0,ah1,ah2,ah3, bl0,bl1);
                mma16816(acc[nt][0],acc[nt][1],acc[nt][2],acc[nt][3], al0,al1,al2,al3, bh0,bh1);
            }
        }
    }
    CPA_WAIT(0);

    float* P = g_part + (size_t)ky*G4*64;
    const int m0 = g0 + warp*16 + gid, m1 = m0 + 8;
    #pragma unroll
    for (int nt=0; nt<8; nt++){
        const int n0 = nt*8 + tg*2;
        *(float2*)&P[(size_t)m0*64 + n0] = make_float2(acc[nt][0], acc[nt][1]);
        *(float2*)&P[(size_t)m1*64 + n0] = make_float2(acc[nt][2], acc[nt][3]);
    }
}

// ---------------------------------------------------------------------------
// Kernel 4: K-split reduce + biases + LSTM cell (unchanged)
// ---------------------------------------------------------------------------
__global__ void lstm_kernel(const float* __restrict__ prev_c, const int* __restrict__ lengths,
                            const float* __restrict__ b_ih, const float* __restrict__ b_hh,
                            float* __restrict__ out)
{
    const int id = blockIdx.x*256 + threadIdx.x;
    const int b = id & 63, h = id >> 6;
    float s[4] = {0.f,0.f,0.f,0.f};
    #pragma unroll
    for (int ky=0; ky<KSPLIT; ++ky){
        const float* P = g_part + (size_t)ky*G4*64;
        #pragma unroll
        for (int g=0; g<4; ++g) s[g] += P[(size_t)(g*1024 + h)*64 + b];
    }
    #pragma unroll
    for (int g=0; g<4; ++g) s[g] += b_ih[g*1024+h] + b_hh[g*1024+h];
    float ig = 1.f/(1.f + __expf(-s[0]));
    float fg = 1.f/(1.f + __expf(-s[1]));
    float gg = tanhf(s[2]);
    float og = 1.f/(1.f + __expf(-s[3]));
    float c0 = prev_c[(size_t)b*HH + h];
    float c1 = fg*c0 + ig*gg;
    float h1 = og*tanhf(c1);
    if (lengths[b] == 0){ c1 = 0.f; h1 = 0.f; }
    out[OUT_H1 + b*HH + h] = h1;
    out[OUT_C1 + b*HH + h] = c1;
    g_h1bf[(size_t)b*HH + h] = __float2bfloat16(h1);
}

// ---------------------------------------------------------------------------
// Kernel 5: logits GEMM, cp.async 4-stage pipeline.
// ---------------------------------------------------------------------------
#define L_STAGES 4
#define L_ABYTES2 20480
#define L_STBYTES 25600
#define SC_PITCH 132
#define L_SMEM 102400                // 4 * 25600

extern "C" __global__ __launch_bounds__(256) void logits_gemm_ca(
    const float* __restrict__ W_out, const float* __restrict__ b_out, float* __restrict__ out)
{
    extern __shared__ __align__(16) unsigned char dyn[];
    const int tid = threadIdx.x, lane = tid & 31, warp = tid >> 5;
    const int gid = lane >> 2, tg = lane & 3;
    const int vb = blockIdx.x * 128;
    const uint32_t smb = (uint32_t)__cvta_generic_to_shared(dyn);

    const int arow = tid >> 1, aseg = tid & 1;
    const int brow = tid >> 2, bseg = tid & 3;
    const float* Asrc = W_out + (size_t)(vb + arow)*HH + aseg*16;
    const __nv_bfloat16* Bsrc = g_h1bf + (size_t)brow*HH + bseg*8;

    const int NCH = HH/32;   // 32

    #pragma unroll
    for (int t=0; t<L_STAGES-1; ++t){
        const uint32_t st = smb + t*L_STBYTES;
        #pragma unroll
        for (int j=0;j<4;j++)
            cpa16(st + arow*160 + aseg*64 + j*16, Asrc + t*32 + j*4);
        cpa16(st + L_ABYTES2 + brow*80 + bseg*16, Bsrc + t*32);
        CPA_COMMIT();
    }

    float acc[8][4];
    #pragma unroll
    for (int nt=0; nt<8; nt++){ acc[nt][0]=0.f; acc[nt][1]=0.f; acc[nt][2]=0.f; acc[nt][3]=0.f; }

    for (int t=0; t<NCH; ++t){
        CPA_WAIT(2);          // oldest group (chunk t) complete; <=2 younger in flight
        __syncthreads();
        if (t + L_STAGES - 1 < NCH){
            const int tn = t + L_STAGES - 1;
            const uint32_t st = smb + (tn % L_STAGES)*L_STBYTES;
            #pragma unroll
            for (int j=0;j<4;j++)
                cpa16(st + arow*160 + aseg*64 + j*16, Asrc + tn*32 + j*4);
            cpa16(st + L_ABYTES2 + brow*80 + bseg*16, Bsrc + tn*32);
        }
        CPA_COMMIT();

        const int p = t % L_STAGES;
        const float* Af = (const float*)(dyn + p*L_STBYTES);
        const __nv_bfloat16* Bt = (const __nv_bfloat16*)(dyn + p*L_STBYTES + L_ABYTES2);
        const int m0 = warp*16 + gid;
        #pragma unroll
        for (int s=0; s<2; ++s){
            const int c0 = s*16 + tg*2;
            float2 f0 = *(const float2*)&Af[(size_t)m0*40 + c0];
            float2 f1 = *(const float2*)&Af[(size_t)(m0+8)*40 + c0];
            float2 f2 = *(const float2*)&Af[(size_t)m0*40 + c0 + 8];
            float2 f3 = *(const float2*)&Af[(size_t)(m0+8)*40 + c0 + 8];
            uint32_t a0 = cvt2bf(f0.x, f0.y);
            uint32_t a1 = cvt2bf(f1.x, f1.y);
            uint32_t a2 = cvt2bf(f2.x, f2.y);
            uint32_t a3 = cvt2bf(f3.x, f3.y);
            #pragma unroll
            for (int nt=0; nt<8; nt++){
                const int bo = (nt*8 + gid)*40 + s*16 + tg*2;
                uint32_t b0 = *(const uint32_t*)(Bt + bo);
                uint32_t b1 = *(const uint32_t*)(Bt + bo + 8);
                mma16816(acc[nt][0],acc[nt][1],acc[nt][2],acc[nt][3], a0,a1,a2,a3, b0,b1);
            }
        }
    }
    CPA_WAIT(0);
    __syncthreads();

    float* scf = (float*)dyn;
    const int m0 = warp*16 + gid, m1 = m0 + 8;
    const float bo0 = b_out[vb + m0];
    const float bo1 = b_out[vb + m1];
    #pragma unroll
    for (int nt=0; nt<8; nt++){
        const int n0 = nt*8 + tg*2;
        scf[(size_t)(n0  )*SC_PITCH + m0] = acc[nt][0] + bo0;
        scf[(size_t)(n0+1)*SC_PITCH + m0] = acc[nt][1] + bo0;
        scf[(size_t)(n0  )*SC_PITCH + m1] = acc[nt][2] + bo1;
        scf[(size_t)(n0+1)*SC_PITCH + m1] = acc[nt][3] + bo1;
    }
    __syncthreads();
    const int b = tid>>2, qq = tid&3;
    float* orow = out + (size_t)b*VV + vb;
    #pragma unroll
    for (int i=0;i<8;i++){
        const int f = qq*8 + i;
        *(float4*)&orow[f*4] = *(const float4*)&scf[(size_t)b*SC_PITCH + f*4];
    }
}

// ---------------------------------------------------------------------------
// Kernel 6: logsoftmax partials. grid (64,4), 1024 thr.
// ---------------------------------------------------------------------------
__global__ __launch_bounds__(1024) void ls_partial(const float* __restrict__ out)
{
    __shared__ float red[33];
    const int b = blockIdx.x, q = blockIdx.y;
    const int tid = threadIdx.x, lane = tid & 31, warp = tid >> 5;
    const float* row = out + (size_t)b*VV + q*8000;
    float4 vals[2];
    float m = -3.0e38f;
    #pragma unroll
    for (int j=0;j<2;j++){
        const int i4 = tid + j*1024;
        if (i4 < 2000){
            vals[j] = *(const float4*)&row[i4*4];
            m = fmaxf(m, fmaxf(fmaxf(vals[j].x, vals[j].y), fmaxf(vals[j].z, vals[j].w)));
        } else vals[j] = make_float4(-3.0e38f,-3.0e38f,-3.0e38f,-3.0e38f);
    }
    #pragma unroll
    for (int o=16;o;o>>=1) m = fmaxf(m, __shfl_xor_sync(0xffffffffu, m, o));
    if (lane==0) red[warp] = m;
    __syncthreads();
    if (warp==0){
        float v = red[lane];
        #pragma unroll
        for (int o=16;o;o>>=1) v = fmaxf(v, __shfl_xor_sync(0xffffffffu, v, o));
        if (lane==0) red[32] = v;
    }
    __syncthreads();
    m = red[32];
    __syncthreads();
    float z = 0.f;
    #pragma unroll
    for (int j=0;j<2;j++){
        const int i4 = tid + j*1024;
        if (i4 < 2000)
            z += __expf(vals[j].x - m) + __expf(vals[j].y - m)
               + __expf(vals[j].z - m) + __expf(vals[j].w - m);
    }
    #pragma unroll
    for (int o=16;o;o>>=1) z += __shfl_xor_sync(0xffffffffu, z, o);
    if (lane==0) red[warp] = z;
    __syncthreads();
    if (warp==0){
        float v = red[lane];
        #pragma unroll
        for (int o=16;o;o>>=1) v += __shfl_xor_sync(0xffffffffu, v, o);
        if (lane==0){ g_pmax[b*4+q] = m; g_psum[b*4+q] = v; }
    }
}

// ---------------------------------------------------------------------------
// Kernel 7: subtract lse (combine inlined: 8 scalar reads per block).
// ---------------------------------------------------------------------------
__global__ __launch_bounds__(1024) void ls_norm(float* __restrict__ out)
{
    const int b = blockIdx.x, q = blockIdx.y;
    const int tid = threadIdx.x;
    float m = g_pmax[b*4];
    #pragma unroll
    for (int k=1;k<4;k++) m = fmaxf(m, g_pmax[b*4+k]);
    float s = 0.f;
    #pragma unroll
    for (int k=0;k<4;k++) s += g_psum[b*4+k] * __expf(g_pmax[b*4+k] - m);
    const float lse = m + logf(s);
    float* row = out + (size_t)b*VV + q*8000;
    #pragma unroll
    for (int j=0;j<2;j++){
        const int i4 = tid + j*1024;
        if (i4 < 2000){
            float4 v = *(const float4*)&row[i4*4];
            v.x -= lse; v.y -= lse; v.z -= lse; v.w -= lse;
            *(float4*)&row[i4*4] = v;
        }
    }
}

// ---------------------------------------------------------------------------
extern "C" void kernel_launch(void* const* d_in, const int* in_sizes, int n_in,
                              void* d_out, int out_size)
{
    const int*   input_batch = (const int*)  d_in[0];
    const float* prev_h      = (const float*)d_in[1];
    const float* prev_c      = (const float*)d_in[2];
    const float* enc         = (const float*)d_in[3];
    const int*   lengths     = (const int*)  d_in[4];
    const float* emb         = (const float*)d_in[5];
    const float* attn_w      = (const float*)d_in[6];
    const float* attn_b      = (const float*)d_in[7];
    const float* W_ih        = (const float*)d_in[8];
    const float* W_hh        = (const float*)d_in[9];
    const float* b_ih        = (const float*)d_in[10];
    const float* b_hh        = (const float*)d_in[11];
    const float* W_out       = (const float*)d_in[12];
    const float* b_out       = (const float*)d_in[13];
    float* out = (float*)d_out;

    cudaFuncSetAttribute(logits_gemm_ca, cudaFuncAttributeMaxDynamicSharedMemorySize, L_SMEM);
    cudaFuncSetAttribute(gates_gemm_ca,  cudaFuncAttributeMaxDynamicSharedMemorySize, GS_SMEM);

    attn_partial<<<dim3(64,4), 256>>>(prev_h, enc, attn_w, attn_b);
    attn_combine<<<64, 256>>>(input_batch, prev_h, emb, out);
    gates_gemm_ca<<<dim3(32, KSPLIT), 256, GS_SMEM>>>(W_ih, W_hh);
    lstm_kernel<<<256, 256>>>(prev_c, lengths, b_ih, b_hh, out);
    logits_gemm_ca<<<250, 256, L_SMEM>>>(W_out, b_out, out);
    ls_partial<<<dim3(64,4), 1024>>>(out);
    ls_norm<<<dim3(64,4), 1024>>>(out);
}

// round 16
// speedup vs baseline: 1.6428x; 1.0158x over previous
#include <cuda_runtime.h>
#include <cuda_bf16.h>
#include <cstdint>
#include <math.h>

// Problem dims
#define BB 64
#define HH 1024
#define SS 128
#define VV 32000
#define KCAT 3072      // E + H + H (emb | context | h0)
#define G4 4096        // 4*H
#define KSPLIT 6
#define NLB 250        // logits blocks

// d_out layout (floats)
#define OUT_H1   (64*32000)
#define OUT_C1   (OUT_H1 + 64*1024)
#define OUT_ATTN (OUT_C1 + 64*1024)

// Scratch (no allocation allowed -> device globals)
__device__ __align__(16) __nv_bfloat16 g_xh[BB*KCAT];  // [b][k] hi: emb|ctx|h0
__device__ __align__(16) __nv_bfloat16 g_xl[BB*KCAT];  // [b][k] lo
__device__ __align__(16) __nv_bfloat16 g_h1bf[BB*HH];  // h1 bf16, [b][k]
__device__ __align__(16) float g_part[KSPLIT*G4*BB];   // gates K-split partials
__device__ __align__(16) float g_scores[BB*SS];        // attention raw scores
__device__ __align__(16) float g_actx[BB*4*HH];        // attn partial context
__device__ float g_am[BB*4];                            // attn partial max
__device__ float g_aZ[BB*4];                            // attn partial Z
__device__ __align__(16) float g_pm[BB*NLB];            // per-block logit max
__device__ __align__(16) float g_ps[BB*NLB];            // per-block logit sumexp

typedef unsigned long long ull;
__device__ __forceinline__ void mma16816(float& c0, float& c1, float& c2, float& c3,
                                         uint32_t a0, uint32_t a1, uint32_t a2, uint32_t a3,
                                         uint32_t b0, uint32_t b1){
    asm("mma.sync.aligned.m16n8k16.row.col.f32.bf16.bf16.f32 "
        "{%0,%1,%2,%3},{%4,%5,%6,%7},{%8,%9},{%0,%1,%2,%3};"
        : "+f"(c0), "+f"(c1), "+f"(c2), "+f"(c3)
        : "r"(a0), "r"(a1), "r"(a2), "r"(a3), "r"(b0), "r"(b1));
}
__device__ __forceinline__ uint32_t cvt2bf(float lo, float hi){
    __nv_bfloat162 h = __floats2bfloat162_rn(lo, hi);   // .x = lo
    return *(uint32_t*)&h;
}
__device__ __forceinline__ void split2(float x, float y, uint32_t& hi, uint32_t& lo){
    __nv_bfloat162 h = __floats2bfloat162_rn(x, y);
    float rx = x - __bfloat162float(h.x);
    float ry = y - __bfloat162float(h.y);
    __nv_bfloat162 l = __floats2bfloat162_rn(rx, ry);
    hi = *(uint32_t*)&h; lo = *(uint32_t*)&l;
}
__device__ __forceinline__ void splitbf(float x, __nv_bfloat16* ph, __nv_bfloat16* pl){
    __nv_bfloat16 h = __float2bfloat16(x);
    *ph = h;
    *pl = __float2bfloat16(x - __bfloat162float(h));
}
__device__ __forceinline__ void cpa16(uint32_t dst, const void* src){
    asm volatile("cp.async.cg.shared.global [%0], [%1], 16;" :: "r"(dst), "l"(src));
}
#define CPA_COMMIT() asm volatile("cp.async.commit_group;" ::: "memory")
#define CPA_WAIT(n)  asm volatile("cp.async.wait_group %0;" :: "n"(n) : "memory")

// ---------------------------------------------------------------------------
// Kernel 1: fused flash-style attention partial. grid (64,4), 256 thr. (unchanged)
// ---------------------------------------------------------------------------
__global__ __launch_bounds__(256) void attn_partial(const float* __restrict__ prev_h,
                                                    const float* __restrict__ enc,
                                                    const float* __restrict__ attn_w,
                                                    const float* __restrict__ attn_b)
{
    __shared__ float sw2[1024];
    __shared__ float red[40];
    __shared__ float s_m[8], s_Z[8];
    __shared__ float s_ctx[8][1024];
    const int b = blockIdx.x, q = blockIdx.y;
    const int tid = threadIdx.x, lane = tid & 31, warp = tid >> 5;

    float hacc = 0.f;
    #pragma unroll
    for (int k = 0; k < 4; k++){
        const int i = tid + k*256;
        hacc += attn_w[i] * prev_h[(size_t)b*1024 + i];
        sw2[i] = attn_w[1024 + i];
    }
    #pragma unroll
    for (int o=16;o;o>>=1) hacc += __shfl_xor_sync(0xffffffffu, hacc, o);
    if (lane==0) red[warp] = hacc;
    __syncthreads();
    if (tid==0){ float s=0.f; for (int w=0;w<8;w++) s+=red[w]; red[32] = s + attn_b[0]; }
    __syncthreads();
    const float hpb = red[32];

    const float* encb = enc + (size_t)b*SS*HH;
    float m = -3.0e38f, Z = 0.f;
    float ctx[32];
    #pragma unroll
    for (int j=0;j<32;j++) ctx[j] = 0.f;

    #pragma unroll
    for (int r=0;r<4;r++){
        const int s = q*32 + warp*4 + r;
        const float* ep = encb + (size_t)s*1024;
        float row[32];
        float dot = 0.f;
        #pragma unroll
        for (int j=0;j<32;j++){
            row[j] = ep[lane + j*32];
            dot += row[j]*sw2[lane + j*32];
        }
        #pragma unroll
        for (int o=16;o;o>>=1) dot += __shfl_xor_sync(0xffffffffu, dot, o);
        const float sc = dot + hpb;
        if (lane==0) g_scores[b*128 + s] = sc;
        const float mn = fmaxf(m, sc);
        const float scale = __expf(m - mn);
        const float c = __expf(sc - mn);
        Z = Z*scale + c;
        #pragma unroll
        for (int j=0;j<32;j++) ctx[j] = ctx[j]*scale + c*row[j];
        m = mn;
    }
    if (lane==0){ s_m[warp] = m; s_Z[warp] = Z; }
    #pragma unroll
    for (int j=0;j<32;j++) s_ctx[warp][j*32 + lane] = ctx[j];
    __syncthreads();

    float mb = s_m[0];
    #pragma unroll
    for (int w=1;w<8;w++) mb = fmaxf(mb, s_m[w]);
    if (tid < 8) red[tid] = s_Z[tid]*__expf(s_m[tid] - mb);
    __syncthreads();
    if (tid==0){ float z=0.f; for (int w=0;w<8;w++) z+=red[w]; red[32]=z; }
    __syncthreads();
    const float Zb = red[32];

    float* cp = g_actx + (size_t)(b*4 + q)*1024;
    #pragma unroll
    for (int k=0;k<4;k++){
        const int i = tid + k*256;
        float acc = 0.f;
        #pragma unroll
        for (int w=0;w<8;w++) acc += s_ctx[w][i]*__expf(s_m[w] - mb);
        cp[i] = acc;
    }
    if (tid==0){ g_am[b*4+q] = mb; g_aZ[b*4+q] = Zb; }
}

// ---------------------------------------------------------------------------
// Kernel 2: attention combine + bf16 prep. grid 64, 256 thr. (unchanged)
// ---------------------------------------------------------------------------
__global__ __launch_bounds__(256) void attn_combine(const int* __restrict__ input_batch,
                                                    const float* __restrict__ prev_h,
                                                    const float* __restrict__ emb,
                                                    float* __restrict__ out)
{
    const int b = blockIdx.x, tid = threadIdx.x;
    const int tok = input_batch[b];
    __nv_bfloat16* xh = g_xh + (size_t)b*KCAT;
    __nv_bfloat16* xl = g_xl + (size_t)b*KCAT;

    float m = g_am[b*4];
    #pragma unroll
    for (int q=1;q<4;q++) m = fmaxf(m, g_am[b*4+q]);
    float e0 = __expf(g_am[b*4+0] - m);
    float e1 = __expf(g_am[b*4+1] - m);
    float e2 = __expf(g_am[b*4+2] - m);
    float e3 = __expf(g_am[b*4+3] - m);
    const float Z = g_aZ[b*4+0]*e0 + g_aZ[b*4+1]*e1 + g_aZ[b*4+2]*e2 + g_aZ[b*4+3]*e3;
    const float invZ = 1.f/Z;

    if (tid < 128)
        out[OUT_ATTN + b*128 + tid] = __expf(g_scores[b*128 + tid] - m)*invZ;

    const float* cp = g_actx + (size_t)b*4*1024;
    #pragma unroll
    for (int k=0;k<4;k++){
        const int i = tid + k*256;
        float c = (cp[i]*e0 + cp[1024+i]*e1 + cp[2048+i]*e2 + cp[3072+i]*e3)*invZ;
        splitbf(c, xh + 1024 + i, xl + 1024 + i);
        splitbf(prev_h[(size_t)b*1024 + i], xh + 2048 + i, xl + 2048 + i);
        splitbf(emb[(size_t)tok*1024 + i], xh + i, xl + i);
    }
}

// ---------------------------------------------------------------------------
// Kernel 3: gates GEMM, cp.async 3-stage pipeline (unchanged; proven)
// ---------------------------------------------------------------------------
#define GS_STAGES 3
#define GS_BHOFF 20480
#define GS_BLOFF 25600
#define GS_ST 30720
#define GS_SMEM 92160

extern "C" __global__ __launch_bounds__(256) void gates_gemm_ca(
    const float* __restrict__ W_ih, const float* __restrict__ W_hh)
{
    extern __shared__ __align__(16) unsigned char dyn[];
    const int tid = threadIdx.x, lane = tid & 31, warp = tid >> 5;
    const int gid = lane >> 2, tg = lane & 3;
    const int g0 = blockIdx.x * 128;
    const int ky = blockIdx.y;
    const bool ih = (ky < 4);
    const uint32_t smb = (uint32_t)__cvta_generic_to_shared(dyn);

    const int arow = tid >> 1, aseg = tid & 1;
    const int brow = tid >> 2, bseg = tid & 3;
    const float* Asrc = ih ? (W_ih + (size_t)(g0 + arow)*2048 + ky*512 + aseg*16)
                           : (W_hh + (size_t)(g0 + arow)*1024 + (ky-4)*512 + aseg*16);
    const int kb = ky*512;
    const __nv_bfloat16* Bsh = g_xh + (size_t)brow*KCAT + kb + bseg*8;
    const __nv_bfloat16* Bsl = g_xl + (size_t)brow*KCAT + kb + bseg*8;

    const int NCH = 512/32;   // 16

    #pragma unroll
    for (int t=0; t<GS_STAGES-1; ++t){
        const uint32_t st = smb + t*GS_ST;
        #pragma unroll
        for (int j=0;j<4;j++)
            cpa16(st + arow*160 + aseg*64 + j*16, Asrc + t*32 + j*4);
        cpa16(st + GS_BHOFF + brow*80 + bseg*16, Bsh + t*32);
        cpa16(st + GS_BLOFF + brow*80 + bseg*16, Bsl + t*32);
        CPA_COMMIT();
    }

    float acc[8][4];
    #pragma unroll
    for (int nt=0; nt<8; nt++){ acc[nt][0]=0.f; acc[nt][1]=0.f; acc[nt][2]=0.f; acc[nt][3]=0.f; }

    for (int t=0; t<NCH; ++t){
        CPA_WAIT(1);
        __syncthreads();
        if (t + GS_STAGES - 1 < NCH){
            const int tn = t + GS_STAGES - 1;
            const uint32_t st = smb + (tn % GS_STAGES)*GS_ST;
            #pragma unroll
            for (int j=0;j<4;j++)
                cpa16(st + arow*160 + aseg*64 + j*16, Asrc + tn*32 + j*4);
            cpa16(st + GS_BHOFF + brow*80 + bseg*16, Bsh + tn*32);
            cpa16(st + GS_BLOFF + brow*80 + bseg*16, Bsl + tn*32);
        }
        CPA_COMMIT();

        const int p = t % GS_STAGES;
        const float* Af = (const float*)(dyn + p*GS_ST);
        const __nv_bfloat16* Bth = (const __nv_bfloat16*)(dyn + p*GS_ST + GS_BHOFF);
        const __nv_bfloat16* Btl = (const __nv_bfloat16*)(dyn + p*GS_ST + GS_BLOFF);
        const int m0 = warp*16 + gid;
        #pragma unroll
        for (int s=0; s<2; ++s){
            const int c0 = s*16 + tg*2;
            float2 f0 = *(const float2*)&Af[(size_t)m0*40 + c0];
            float2 f1 = *(const float2*)&Af[(size_t)(m0+8)*40 + c0];
            float2 f2 = *(const float2*)&Af[(size_t)m0*40 + c0 + 8];
            float2 f3 = *(const float2*)&Af[(size_t)(m0+8)*40 + c0 + 8];
            uint32_t ah0,al0, ah1,al1, ah2,al2, ah3,al3;
            split2(f0.x, f0.y, ah0, al0);
            split2(f1.x, f1.y, ah1, al1);
            split2(f2.x, f2.y, ah2, al2);
            split2(f3.x, f3.y, ah3, al3);
            #pragma unroll
            for (int nt=0; nt<8; nt++){
                const int bo = (nt*8 + gid)*40 + s*16 + tg*2;
                uint32_t bh0 = *(const uint32_t*)(Bth + bo);
                uint32_t bh1 = *(const uint32_t*)(Bth + bo + 8);
                uint32_t bl0 = *(const uint32_t*)(Btl + bo);
                uint32_t bl1 = *(const uint32_t*)(Btl + bo + 8);
                mma16816(acc[nt][0],acc[nt][1],acc[nt][2],acc[nt][3], ah0,ah1,ah2,ah3, bh0,bh1);
                mma16816(acc[nt][0],acc[nt][1],acc[nt][2],acc[nt][3], ah0,ah1,ah2,ah3, bl0,bl1);
                mma16816(acc[nt][0],acc[nt][1],acc[nt][2],acc[nt][3], al0,al1,al2,al3, bh0,bh1);
            }
        }
    }
    CPA_WAIT(0);

    float* P = g_part + (size_t)ky*G4*64;
    const int m0 = g0 + warp*16 + gid, m1 = m0 + 8;
    #pragma unroll
    for (int nt=0; nt<8; nt++){
        const int n0 = nt*8 + tg*2;
        *(float2*)&P[(size_t)m0*64 + n0] = make_float2(acc[nt][0], acc[nt][1]);
        *(float2*)&P[(size_t)m1*64 + n0] = make_float2(acc[nt][2], acc[nt][3]);
    }
}

// ---------------------------------------------------------------------------
// Kernel 4: K-split reduce + biases + LSTM cell (unchanged)
// ---------------------------------------------------------------------------
__global__ void lstm_kernel(const float* __restrict__ prev_c, const int* __restrict__ lengths,
                            const float* __restrict__ b_ih, const float* __restrict__ b_hh,
                            float* __restrict__ out)
{
    const int id = blockIdx.x*256 + threadIdx.x;
    const int b = id & 63, h = id >> 6;
    float s[4] = {0.f,0.f,0.f,0.f};
    #pragma unroll
    for (int ky=0; ky<KSPLIT; ++ky){
        const float* P = g_part + (size_t)ky*G4*64;
        #pragma unroll
        for (int g=0; g<4; ++g) s[g] += P[(size_t)(g*1024 + h)*64 + b];
    }
    #pragma unroll
    for (int g=0; g<4; ++g) s[g] += b_ih[g*1024+h] + b_hh[g*1024+h];
    float ig = 1.f/(1.f + __expf(-s[0]));
    float fg = 1.f/(1.f + __expf(-s[1]));
    float gg = tanhf(s[2]);
    float og = 1.f/(1.f + __expf(-s[3]));
    float c0 = prev_c[(size_t)b*HH + h];
    float c1 = fg*c0 + ig*gg;
    float h1 = og*tanhf(c1);
    if (lengths[b] == 0){ c1 = 0.f; h1 = 0.f; }
    out[OUT_H1 + b*HH + h] = h1;
    out[OUT_C1 + b*HH + h] = c1;
    g_h1bf[(size_t)b*HH + h] = __float2bfloat16(h1);
}

// ---------------------------------------------------------------------------
// Kernel 5: logits GEMM, cp.async 4-stage pipeline + fused logsoftmax partials.
// ---------------------------------------------------------------------------
#define L_STAGES 4
#define L_ABYTES2 20480
#define L_STBYTES 25600
#define SC_PITCH 132
#define L_SMEM 102400                // 4 * 25600

extern "C" __global__ __launch_bounds__(256) void logits_gemm_ca(
    const float* __restrict__ W_out, const float* __restrict__ b_out, float* __restrict__ out)
{
    extern __shared__ __align__(16) unsigned char dyn[];
    const int tid = threadIdx.x, lane = tid & 31, warp = tid >> 5;
    const int gid = lane >> 2, tg = lane & 3;
    const int vb = blockIdx.x * 128;
    const uint32_t smb = (uint32_t)__cvta_generic_to_shared(dyn);

    const int arow = tid >> 1, aseg = tid & 1;
    const int brow = tid >> 2, bseg = tid & 3;
    const float* Asrc = W_out + (size_t)(vb + arow)*HH + aseg*16;
    const __nv_bfloat16* Bsrc = g_h1bf + (size_t)brow*HH + bseg*8;

    const int NCH = HH/32;   // 32

    #pragma unroll
    for (int t=0; t<L_STAGES-1; ++t){
        const uint32_t st = smb + t*L_STBYTES;
        #pragma unroll
        for (int j=0;j<4;j++)
            cpa16(st + arow*160 + aseg*64 + j*16, Asrc + t*32 + j*4);
        cpa16(st + L_ABYTES2 + brow*80 + bseg*16, Bsrc + t*32);
        CPA_COMMIT();
    }

    float acc[8][4];
    #pragma unroll
    for (int nt=0; nt<8; nt++){ acc[nt][0]=0.f; acc[nt][1]=0.f; acc[nt][2]=0.f; acc[nt][3]=0.f; }

    for (int t=0; t<NCH; ++t){
        CPA_WAIT(2);
        __syncthreads();
        if (t + L_STAGES - 1 < NCH){
            const int tn = t + L_STAGES - 1;
            const uint32_t st = smb + (tn % L_STAGES)*L_STBYTES;
            #pragma unroll
            for (int j=0;j<4;j++)
                cpa16(st + arow*160 + aseg*64 + j*16, Asrc + tn*32 + j*4);
            cpa16(st + L_ABYTES2 + brow*80 + bseg*16, Bsrc + tn*32);
        }
        CPA_COMMIT();

        const int p = t % L_STAGES;
        const float* Af = (const float*)(dyn + p*L_STBYTES);
        const __nv_bfloat16* Bt = (const __nv_bfloat16*)(dyn + p*L_STBYTES + L_ABYTES2);
        const int m0 = warp*16 + gid;
        #pragma unroll
        for (int s=0; s<2; ++s){
            const int c0 = s*16 + tg*2;
            float2 f0 = *(const float2*)&Af[(size_t)m0*40 + c0];
            float2 f1 = *(const float2*)&Af[(size_t)(m0+8)*40 + c0];
            float2 f2 = *(const float2*)&Af[(size_t)m0*40 + c0 + 8];
            float2 f3 = *(const float2*)&Af[(size_t)(m0+8)*40 + c0 + 8];
            uint32_t a0 = cvt2bf(f0.x, f0.y);
            uint32_t a1 = cvt2bf(f1.x, f1.y);
            uint32_t a2 = cvt2bf(f2.x, f2.y);
            uint32_t a3 = cvt2bf(f3.x, f3.y);
            #pragma unroll
            for (int nt=0; nt<8; nt++){
                const int bo = (nt*8 + gid)*40 + s*16 + tg*2;
                uint32_t b0 = *(const uint32_t*)(Bt + bo);
                uint32_t b1 = *(const uint32_t*)(Bt + bo + 8);
                mma16816(acc[nt][0],acc[nt][1],acc[nt][2],acc[nt][3], a0,a1,a2,a3, b0,b1);
            }
        }
    }
    CPA_WAIT(0);
    __syncthreads();

    float* scf = (float*)dyn;   // [64][SC_PITCH]
    const int m0 = warp*16 + gid, m1 = m0 + 8;
    const float bo0 = b_out[vb + m0];
    const float bo1 = b_out[vb + m1];
    #pragma unroll
    for (int nt=0; nt<8; nt++){
        const int n0 = nt*8 + tg*2;
        scf[(size_t)(n0  )*SC_PITCH + m0] = acc[nt][0] + bo0;
        scf[(size_t)(n0+1)*SC_PITCH + m0] = acc[nt][1] + bo0;
        scf[(size_t)(n0  )*SC_PITCH + m1] = acc[nt][2] + bo1;
        scf[(size_t)(n0+1)*SC_PITCH + m1] = acc[nt][3] + bo1;
    }
    __syncthreads();
    const int b = tid>>2, qq = tid&3;
    float* orow = out + (size_t)b*VV + vb;
    #pragma unroll
    for (int i=0;i<8;i++){
        const int f = qq*8 + i;
        *(float4*)&orow[f*4] = *(const float4*)&scf[(size_t)b*SC_PITCH + f*4];
    }

    // fused logsoftmax partial: per batch row b, max+sumexp over this block's
    // 128 v-columns (tile already in scf). 4 adjacent lanes share one b.
    {
        const float* rowp = &scf[(size_t)b*SC_PITCH + qq*32];
        float vm = rowp[0];
        #pragma unroll
        for (int i=1;i<32;i++) vm = fmaxf(vm, rowp[i]);
        vm = fmaxf(vm, __shfl_xor_sync(0xffffffffu, vm, 1));
        vm = fmaxf(vm, __shfl_xor_sync(0xffffffffu, vm, 2));
        float z = 0.f;
        #pragma unroll
        for (int i=0;i<32;i++) z += __expf(rowp[i] - vm);
        z += __shfl_xor_sync(0xffffffffu, z, 1);
        z += __shfl_xor_sync(0xffffffffu, z, 2);
        if (qq == 0){
            g_pm[(size_t)b*NLB + blockIdx.x] = vm;
            g_ps[(size_t)b*NLB + blockIdx.x] = z;
        }
    }
}

// ---------------------------------------------------------------------------
// Kernel 6: combine 250 (m,Z) partials + subtract lse. grid (64,4), 1024 thr.
// ---------------------------------------------------------------------------
__global__ __launch_bounds__(1024) void ls_norm(float* __restrict__ out)
{
    __shared__ float sm_[32], sz_[32];
    const int b = blockIdx.x, q = blockIdx.y;
    const int tid = threadIdx.x, lane = tid & 31, warp = tid >> 5;

    float m = -3.0e38f, z = 0.f;
    if (tid < NLB){
        m = g_pm[(size_t)b*NLB + tid];
        z = g_ps[(size_t)b*NLB + tid];
    }
    #pragma unroll
    for (int o=16;o;o>>=1){
        float om = __shfl_xor_sync(0xffffffffu, m, o);
        float oz = __shfl_xor_sync(0xffffffffu, z, o);
        float nm = fmaxf(m, om);
        z = z*__expf(m - nm) + oz*__expf(om - nm);
        m = nm;
    }
    if (lane==0){ sm_[warp] = m; sz_[warp] = z; }
    __syncthreads();
    if (warp==0){
        m = sm_[lane]; z = sz_[lane];
        #pragma unroll
        for (int o=16;o;o>>=1){
            float om = __shfl_xor_sync(0xffffffffu, m, o);
            float oz = __shfl_xor_sync(0xffffffffu, z, o);
            float nm = fmaxf(m, om);
            z = z*__expf(m - nm) + oz*__expf(om - nm);
            m = nm;
        }
        if (lane==0){ sm_[0] = m + logf(z); }
    }
    __syncthreads();
    const float lse = sm_[0];

    float* row = out + (size_t)b*VV + q*8000;
    #pragma unroll
    for (int j=0;j<2;j++){
        const int i4 = tid + j*1024;
        if (i4 < 2000){
            float4 v = *(const float4*)&row[i4*4];
            v.x -= lse; v.y -= lse; v.z -= lse; v.w -= lse;
            *(float4*)&row[i4*4] = v;
        }
    }
}

// ---------------------------------------------------------------------------
extern "C" void kernel_launch(void* const* d_in, const int* in_sizes, int n_in,
                              void* d_out, int out_size)
{
    const int*   input_batch = (const int*)  d_in[0];
    const float* prev_h      = (const float*)d_in[1];
    const float* prev_c      = (const float*)d_in[2];
    const float* enc         = (const float*)d_in[3];
    const int*   lengths     = (const int*)  d_in[4];
    const float* emb         = (const float*)d_in[5];
    const float* attn_w      = (const float*)d_in[6];
    const float* attn_b      = (const float*)d_in[7];
    const float* W_ih        = (const float*)d_in[8];
    const float* W_hh        = (const float*)d_in[9];
    const float* b_ih        = (const float*)d_in[10];
    const float* b_hh        = (const float*)d_in[11];
    const float* W_out       = (const float*)d_in[12];
    const float* b_out       = (const float*)d_in[13];
    float* out = (float*)d_out;

    cudaFuncSetAttribute(logits_gemm_ca, cudaFuncAttributeMaxDynamicSharedMemorySize, L_SMEM);
    cudaFuncSetAttribute(gates_gemm_ca,  cudaFuncAttributeMaxDynamicSharedMemorySize, GS_SMEM);

    attn_partial<<<dim3(64,4), 256>>>(prev_h, enc, attn_w, attn_b);
    attn_combine<<<64, 256>>>(input_batch, prev_h, emb, out);
    gates_gemm_ca<<<dim3(32, KSPLIT), 256, GS_SMEM>>>(W_ih, W_hh);
    lstm_kernel<<<256, 256>>>(prev_c, lengths, b_ih, b_hh, out);
    logits_gemm_ca<<<NLB, 256, L_SMEM>>>(W_out, b_out, out);
    ls_norm<<<dim3(64,4), 1024>>>(out);
}

// round 17
// speedup vs baseline: 1.7101x; 1.0410x over previous
#include <cuda_runtime.h>
#include <cuda_bf16.h>
#include <cstdint>
#include <math.h>

// Problem dims
#define BB 64
#define HH 1024
#define SS 128
#define VV 32000
#define KCAT 3072      // E + H + H (emb | context | h0)
#define G4 4096        // 4*H
#define KSPLIT 6
#define NLB 250        // logits blocks

// d_out layout (floats)
#define OUT_H1   (64*32000)
#define OUT_C1   (OUT_H1 + 64*1024)
#define OUT_ATTN (OUT_C1 + 64*1024)

// Scratch (no allocation allowed -> device globals)
__device__ __align__(16) __nv_bfloat16 g_xh[BB*KCAT];  // [b][k] hi: emb|ctx|h0
__device__ __align__(16) __nv_bfloat16 g_xl[BB*KCAT];  // [b][k] lo
__device__ __align__(16) __nv_bfloat16 g_h1bf[BB*HH];  // h1 bf16, [b][k]
__device__ __align__(16) float g_part[KSPLIT*G4*BB];   // gates K-split partials
__device__ __align__(16) float g_scores[BB*SS];        // attention raw scores
__device__ __align__(16) float g_actx[BB*4*HH];        // attn partial context
__device__ float g_am[BB*4];                            // attn partial max
__device__ float g_aZ[BB*4];                            // attn partial Z
__device__ __align__(16) float g_pm[BB*NLB];            // per-block logit max
__device__ __align__(16) float g_ps[BB*NLB];            // per-block logit sumexp

typedef unsigned long long ull;
__device__ __forceinline__ void mma16816(float& c0, float& c1, float& c2, float& c3,
                                         uint32_t a0, uint32_t a1, uint32_t a2, uint32_t a3,
                                         uint32_t b0, uint32_t b1){
    asm("mma.sync.aligned.m16n8k16.row.col.f32.bf16.bf16.f32 "
        "{%0,%1,%2,%3},{%4,%5,%6,%7},{%8,%9},{%0,%1,%2,%3};"
        : "+f"(c0), "+f"(c1), "+f"(c2), "+f"(c3)
        : "r"(a0), "r"(a1), "r"(a2), "r"(a3), "r"(b0), "r"(b1));
}
__device__ __forceinline__ uint32_t cvt2bf(float lo, float hi){
    __nv_bfloat162 h = __floats2bfloat162_rn(lo, hi);   // .x = lo
    return *(uint32_t*)&h;
}
__device__ __forceinline__ void split2(float x, float y, uint32_t& hi, uint32_t& lo){
    __nv_bfloat162 h = __floats2bfloat162_rn(x, y);
    float rx = x - __bfloat162float(h.x);
    float ry = y - __bfloat162float(h.y);
    __nv_bfloat162 l = __floats2bfloat162_rn(rx, ry);
    hi = *(uint32_t*)&h; lo = *(uint32_t*)&l;
}
__device__ __forceinline__ void splitbf(float x, __nv_bfloat16* ph, __nv_bfloat16* pl){
    __nv_bfloat16 h = __float2bfloat16(x);
    *ph = h;
    *pl = __float2bfloat16(x - __bfloat162float(h));
}
__device__ __forceinline__ void cpa16(uint32_t dst, const void* src){
    asm volatile("cp.async.cg.shared.global [%0], [%1], 16;" :: "r"(dst), "l"(src));
}
#define CPA_COMMIT() asm volatile("cp.async.commit_group;" ::: "memory")
#define CPA_WAIT(n)  asm volatile("cp.async.wait_group %0;" :: "n"(n) : "memory")

// ---------------------------------------------------------------------------
// Kernel 1: fused flash-style attention partial. grid (64,4), 256 thr.
// ---------------------------------------------------------------------------
__global__ __launch_bounds__(256) void attn_partial(const float* __restrict__ prev_h,
                                                    const float* __restrict__ enc,
                                                    const float* __restrict__ attn_w,
                                                    const float* __restrict__ attn_b)
{
    cudaTriggerProgrammaticLaunchCompletion();
    __shared__ float sw2[1024];
    __shared__ float red[40];
    __shared__ float s_m[8], s_Z[8];
    __shared__ float s_ctx[8][1024];
    const int b = blockIdx.x, q = blockIdx.y;
    const int tid = threadIdx.x, lane = tid & 31, warp = tid >> 5;

    float hacc = 0.f;
    #pragma unroll
    for (int k = 0; k < 4; k++){
        const int i = tid + k*256;
        hacc += attn_w[i] * prev_h[(size_t)b*1024 + i];
        sw2[i] = attn_w[1024 + i];
    }
    #pragma unroll
    for (int o=16;o;o>>=1) hacc += __shfl_xor_sync(0xffffffffu, hacc, o);
    if (lane==0) red[warp] = hacc;
    __syncthreads();
    if (tid==0){ float s=0.f; for (int w=0;w<8;w++) s+=red[w]; red[32] = s + attn_b[0]; }
    __syncthreads();
    const float hpb = red[32];

    const float* encb = enc + (size_t)b*SS*HH;
    float m = -3.0e38f, Z = 0.f;
    float ctx[32];
    #pragma unroll
    for (int j=0;j<32;j++) ctx[j] = 0.f;

    #pragma unroll
    for (int r=0;r<4;r++){
        const int s = q*32 + warp*4 + r;
        const float* ep = encb + (size_t)s*1024;
        float row[32];
        float dot = 0.f;
        #pragma unroll
        for (int j=0;j<32;j++){
            row[j] = ep[lane + j*32];
            dot += row[j]*sw2[lane + j*32];
        }
        #pragma unroll
        for (int o=16;o;o>>=1) dot += __shfl_xor_sync(0xffffffffu, dot, o);
        const float sc = dot + hpb;
        if (lane==0) g_scores[b*128 + s] = sc;
        const float mn = fmaxf(m, sc);
        const float scale = __expf(m - mn);
        const float c = __expf(sc - mn);
        Z = Z*scale + c;
        #pragma unroll
        for (int j=0;j<32;j++) ctx[j] = ctx[j]*scale + c*row[j];
        m = mn;
    }
    if (lane==0){ s_m[warp] = m; s_Z[warp] = Z; }
    #pragma unroll
    for (int j=0;j<32;j++) s_ctx[warp][j*32 + lane] = ctx[j];
    __syncthreads();

    float mb = s_m[0];
    #pragma unroll
    for (int w=1;w<8;w++) mb = fmaxf(mb, s_m[w]);
    if (tid < 8) red[tid] = s_Z[tid]*__expf(s_m[tid] - mb);
    __syncthreads();
    if (tid==0){ float z=0.f; for (int w=0;w<8;w++) z+=red[w]; red[32]=z; }
    __syncthreads();
    const float Zb = red[32];

    float* cp = g_actx + (size_t)(b*4 + q)*1024;
    #pragma unroll
    for (int k=0;k<4;k++){
        const int i = tid + k*256;
        float acc = 0.f;
        #pragma unroll
        for (int w=0;w<8;w++) acc += s_ctx[w][i]*__expf(s_m[w] - mb);
        cp[i] = acc;
    }
    if (tid==0){ g_am[b*4+q] = mb; g_aZ[b*4+q] = Zb; }
}

// ---------------------------------------------------------------------------
// Kernel 2: attention combine + bf16 prep. grid 64, 256 thr. (PDL consumer)
// ---------------------------------------------------------------------------
__global__ __launch_bounds__(256) void attn_combine(const int* __restrict__ input_batch,
                                                    const float* __restrict__ prev_h,
                                                    const float* __restrict__ emb,
                                                    float* __restrict__ out)
{
    cudaTriggerProgrammaticLaunchCompletion();
    cudaGridDependencySynchronize();
    const int b = blockIdx.x, tid = threadIdx.x;
    const int tok = input_batch[b];
    __nv_bfloat16* xh = g_xh + (size_t)b*KCAT;
    __nv_bfloat16* xl = g_xl + (size_t)b*KCAT;

    float m = g_am[b*4];
    #pragma unroll
    for (int q=1;q<4;q++) m = fmaxf(m, g_am[b*4+q]);
    float e0 = __expf(g_am[b*4+0] - m);
    float e1 = __expf(g_am[b*4+1] - m);
    float e2 = __expf(g_am[b*4+2] - m);
    float e3 = __expf(g_am[b*4+3] - m);
    const float Z = g_aZ[b*4+0]*e0 + g_aZ[b*4+1]*e1 + g_aZ[b*4+2]*e2 + g_aZ[b*4+3]*e3;
    const float invZ = 1.f/Z;

    if (tid < 128)
        out[OUT_ATTN + b*128 + tid] = __expf(g_scores[b*128 + tid] - m)*invZ;

    const float* cp = g_actx + (size_t)b*4*1024;
    #pragma unroll
    for (int k=0;k<4;k++){
        const int i = tid + k*256;
        float c = (cp[i]*e0 + cp[1024+i]*e1 + cp[2048+i]*e2 + cp[3072+i]*e3)*invZ;
        splitbf(c, xh + 1024 + i, xl + 1024 + i);
        splitbf(prev_h[(size_t)b*1024 + i], xh + 2048 + i, xl + 2048 + i);
        splitbf(emb[(size_t)tok*1024 + i], xh + i, xl + i);
    }
}

// ---------------------------------------------------------------------------
// Kernel 3: gates GEMM, cp.async 3-stage. PDL: A (weights) prefetch BEFORE
// the grid-dependency sync; B (g_xh/g_xl) staged after.
// ---------------------------------------------------------------------------
#define GS_STAGES 3
#define GS_BHOFF 20480
#define GS_BLOFF 25600
#define GS_ST 30720
#define GS_SMEM 92160

extern "C" __global__ __launch_bounds__(256) void gates_gemm_ca(
    const float* __restrict__ W_ih, const float* __restrict__ W_hh)
{
    cudaTriggerProgrammaticLaunchCompletion();
    extern __shared__ __align__(16) unsigned char dyn[];
    const int tid = threadIdx.x, lane = tid & 31, warp = tid >> 5;
    const int gid = lane >> 2, tg = lane & 3;
    const int g0 = blockIdx.x * 128;
    const int ky = blockIdx.y;
    const bool ih = (ky < 4);
    const uint32_t smb = (uint32_t)__cvta_generic_to_shared(dyn);

    const int arow = tid >> 1, aseg = tid & 1;
    const int brow = tid >> 2, bseg = tid & 3;
    const float* Asrc = ih ? (W_ih + (size_t)(g0 + arow)*2048 + ky*512 + aseg*16)
                           : (W_hh + (size_t)(g0 + arow)*1024 + (ky-4)*512 + aseg*16);
    const int kb = ky*512;
    const __nv_bfloat16* Bsh = g_xh + (size_t)brow*KCAT + kb + bseg*8;
    const __nv_bfloat16* Bsl = g_xl + (size_t)brow*KCAT + kb + bseg*8;

    const int NCH = 512/32;   // 16

    // pre-dependency: weight prefetch for prologue stages (no data dep)
    #pragma unroll
    for (int t=0; t<GS_STAGES-1; ++t){
        const uint32_t st = smb + t*GS_ST;
        #pragma unroll
        for (int j=0;j<4;j++)
            cpa16(st + arow*160 + aseg*64 + j*16, Asrc + t*32 + j*4);
    }
    cudaGridDependencySynchronize();
    // B staging (depends on attn_combine). Group0 = A0+A1+B0, Group1 = B1.
    {
        const uint32_t st0 = smb;
        cpa16(st0 + GS_BHOFF + brow*80 + bseg*16, Bsh);
        cpa16(st0 + GS_BLOFF + brow*80 + bseg*16, Bsl);
        CPA_COMMIT();
        const uint32_t st1 = smb + GS_ST;
        cpa16(st1 + GS_BHOFF + brow*80 + bseg*16, Bsh + 32);
        cpa16(st1 + GS_BLOFF + brow*80 + bseg*16, Bsl + 32);
        CPA_COMMIT();
    }

    float acc[8][4];
    #pragma unroll
    for (int nt=0; nt<8; nt++){ acc[nt][0]=0.f; acc[nt][1]=0.f; acc[nt][2]=0.f; acc[nt][3]=0.f; }

    for (int t=0; t<NCH; ++t){
        CPA_WAIT(1);
        __syncthreads();
        if (t + GS_STAGES - 1 < NCH){
            const int tn = t + GS_STAGES - 1;
            const uint32_t st = smb + (tn % GS_STAGES)*GS_ST;
            #pragma unroll
            for (int j=0;j<4;j++)
                cpa16(st + arow*160 + aseg*64 + j*16, Asrc + tn*32 + j*4);
            cpa16(st + GS_BHOFF + brow*80 + bseg*16, Bsh + tn*32);
            cpa16(st + GS_BLOFF + brow*80 + bseg*16, Bsl + tn*32);
        }
        CPA_COMMIT();

        const int p = t % GS_STAGES;
        const float* Af = (const float*)(dyn + p*GS_ST);
        const __nv_bfloat16* Bth = (const __nv_bfloat16*)(dyn + p*GS_ST + GS_BHOFF);
        const __nv_bfloat16* Btl = (const __nv_bfloat16*)(dyn + p*GS_ST + GS_BLOFF);
        const int m0 = warp*16 + gid;
        #pragma unroll
        for (int s=0; s<2; ++s){
            const int c0 = s*16 + tg*2;
            float2 f0 = *(const float2*)&Af[(size_t)m0*40 + c0];
            float2 f1 = *(const float2*)&Af[(size_t)(m0+8)*40 + c0];
            float2 f2 = *(const float2*)&Af[(size_t)m0*40 + c0 + 8];
            float2 f3 = *(const float2*)&Af[(size_t)(m0+8)*40 + c0 + 8];
            uint32_t ah0,al0, ah1,al1, ah2,al2, ah3,al3;
            split2(f0.x, f0.y, ah0, al0);
            split2(f1.x, f1.y, ah1, al1);
            split2(f2.x, f2.y, ah2, al2);
            split2(f3.x, f3.y, ah3, al3);
            #pragma unroll
            for (int nt=0; nt<8; nt++){
                const int bo = (nt*8 + gid)*40 + s*16 + tg*2;
                uint32_t bh0 = *(const uint32_t*)(Bth + bo);
                uint32_t bh1 = *(const uint32_t*)(Bth + bo + 8);
                uint32_t bl0 = *(const uint32_t*)(Btl + bo);
                uint32_t bl1 = *(const uint32_t*)(Btl + bo + 8);
                mma16816(acc[nt][0],acc[nt][1],acc[nt][2],acc[nt][3], ah0,ah1,ah2,ah3, bh0,bh1);
                mma16816(acc[nt][0],acc[nt][1],acc[nt][2],acc[nt][3], ah0,ah1,ah2,ah3, bl0,bl1);
                mma16816(acc[nt][0],acc[nt][1],acc[nt][2],acc[nt][3], al0,al1,al2,al3, bh0,bh1);
            }
        }
    }
    CPA_WAIT(0);

    float* P = g_part + (size_t)ky*G4*64;
    const int m0 = g0 + warp*16 + gid, m1 = m0 + 8;
    #pragma unroll
    for (int nt=0; nt<8; nt++){
        const int n0 = nt*8 + tg*2;
        *(float2*)&P[(size_t)m0*64 + n0] = make_float2(acc[nt][0], acc[nt][1]);
        *(float2*)&P[(size_t)m1*64 + n0] = make_float2(acc[nt][2], acc[nt][3]);
    }
}

// ---------------------------------------------------------------------------
// Kernel 4: K-split reduce + biases + LSTM cell (PDL consumer)
// ---------------------------------------------------------------------------
__global__ void lstm_kernel(const float* __restrict__ prev_c, const int* __restrict__ lengths,
                            const float* __restrict__ b_ih, const float* __restrict__ b_hh,
                            float* __restrict__ out)
{
    cudaTriggerProgrammaticLaunchCompletion();
    cudaGridDependencySynchronize();
    const int id = blockIdx.x*256 + threadIdx.x;
    const int b = id & 63, h = id >> 6;
    float s[4] = {0.f,0.f,0.f,0.f};
    #pragma unroll
    for (int ky=0; ky<KSPLIT; ++ky){
        const float* P = g_part + (size_t)ky*G4*64;
        #pragma unroll
        for (int g=0; g<4; ++g) s[g] += P[(size_t)(g*1024 + h)*64 + b];
    }
    #pragma unroll
    for (int g=0; g<4; ++g) s[g] += b_ih[g*1024+h] + b_hh[g*1024+h];
    float ig = 1.f/(1.f + __expf(-s[0]));
    float fg = 1.f/(1.f + __expf(-s[1]));
    float gg = tanhf(s[2]);
    float og = 1.f/(1.f + __expf(-s[3]));
    float c0 = prev_c[(size_t)b*HH + h];
    float c1 = fg*c0 + ig*gg;
    float h1 = og*tanhf(c1);
    if (lengths[b] == 0){ c1 = 0.f; h1 = 0.f; }
    out[OUT_H1 + b*HH + h] = h1;
    out[OUT_C1 + b*HH + h] = c1;
    g_h1bf[(size_t)b*HH + h] = __float2bfloat16(h1);
}

// ---------------------------------------------------------------------------
// Kernel 5: logits GEMM, cp.async 4-stage + fused logsoftmax partials.
// PDL: W_out prefetch for 3 prologue stages BEFORE grid-dependency sync.
// ---------------------------------------------------------------------------
#define L_STAGES 4
#define L_ABYTES2 20480
#define L_STBYTES 25600
#define SC_PITCH 132
#define L_SMEM 102400                // 4 * 25600

extern "C" __global__ __launch_bounds__(256) void logits_gemm_ca(
    const float* __restrict__ W_out, const float* __restrict__ b_out, float* __restrict__ out)
{
    cudaTriggerProgrammaticLaunchCompletion();
    extern __shared__ __align__(16) unsigned char dyn[];
    const int tid = threadIdx.x, lane = tid & 31, warp = tid >> 5;
    const int gid = lane >> 2, tg = lane & 3;
    const int vb = blockIdx.x * 128;
    const uint32_t smb = (uint32_t)__cvta_generic_to_shared(dyn);

    const int arow = tid >> 1, aseg = tid & 1;
    const int brow = tid >> 2, bseg = tid & 3;
    const float* Asrc = W_out + (size_t)(vb + arow)*HH + aseg*16;
    const __nv_bfloat16* Bsrc = g_h1bf + (size_t)brow*HH + bseg*8;

    const int NCH = HH/32;   // 32

    // pre-dependency: weight prefetch for prologue stages 0..2
    #pragma unroll
    for (int t=0; t<L_STAGES-1; ++t){
        const uint32_t st = smb + t*L_STBYTES;
        #pragma unroll
        for (int j=0;j<4;j++)
            cpa16(st + arow*160 + aseg*64 + j*16, Asrc + t*32 + j*4);
    }
    cudaGridDependencySynchronize();
    // B staging (depends on lstm). Group0 = A0..A2+B0, Group1 = B1, Group2 = B2.
    #pragma unroll
    for (int t=0; t<L_STAGES-1; ++t){
        const uint32_t st = smb + t*L_STBYTES;
        cpa16(st + L_ABYTES2 + brow*80 + bseg*16, Bsrc + t*32);
        CPA_COMMIT();
    }

    float acc[8][4];
    #pragma unroll
    for (int nt=0; nt<8; nt++){ acc[nt][0]=0.f; acc[nt][1]=0.f; acc[nt][2]=0.f; acc[nt][3]=0.f; }

    for (int t=0; t<NCH; ++t){
        CPA_WAIT(2);
        __syncthreads();
        if (t + L_STAGES - 1 < NCH){
            const int tn = t + L_STAGES - 1;
            const uint32_t st = smb + (tn % L_STAGES)*L_STBYTES;
            #pragma unroll
            for (int j=0;j<4;j++)
                cpa16(st + arow*160 + aseg*64 + j*16, Asrc + tn*32 + j*4);
            cpa16(st + L_ABYTES2 + brow*80 + bseg*16, Bsrc + tn*32);
        }
        CPA_COMMIT();

        const int p = t % L_STAGES;
        const float* Af = (const float*)(dyn + p*L_STBYTES);
        const __nv_bfloat16* Bt = (const __nv_bfloat16*)(dyn + p*L_STBYTES + L_ABYTES2);
        const int m0 = warp*16 + gid;
        #pragma unroll
        for (int s=0; s<2; ++s){
            const int c0 = s*16 + tg*2;
            float2 f0 = *(const float2*)&Af[(size_t)m0*40 + c0];
            float2 f1 = *(const float2*)&Af[(size_t)(m0+8)*40 + c0];
            float2 f2 = *(const float2*)&Af[(size_t)m0*40 + c0 + 8];
            float2 f3 = *(const float2*)&Af[(size_t)(m0+8)*40 + c0 + 8];
            uint32_t a0 = cvt2bf(f0.x, f0.y);
            uint32_t a1 = cvt2bf(f1.x, f1.y);
            uint32_t a2 = cvt2bf(f2.x, f2.y);
            uint32_t a3 = cvt2bf(f3.x, f3.y);
            #pragma unroll
            for (int nt=0; nt<8; nt++){
                const int bo = (nt*8 + gid)*40 + s*16 + tg*2;
                uint32_t b0 = *(const uint32_t*)(Bt + bo);
                uint32_t b1 = *(const uint32_t*)(Bt + bo + 8);
                mma16816(acc[nt][0],acc[nt][1],acc[nt][2],acc[nt][3], a0,a1,a2,a3, b0,b1);
            }
        }
    }
    CPA_WAIT(0);
    __syncthreads();

    float* scf = (float*)dyn;   // [64][SC_PITCH]
    const int m0 = warp*16 + gid, m1 = m0 + 8;
    const float bo0 = b_out[vb + m0];
    const float bo1 = b_out[vb + m1];
    #pragma unroll
    for (int nt=0; nt<8; nt++){
        const int n0 = nt*8 + tg*2;
        scf[(size_t)(n0  )*SC_PITCH + m0] = acc[nt][0] + bo0;
        scf[(size_t)(n0+1)*SC_PITCH + m0] = acc[nt][1] + bo0;
        scf[(size_t)(n0  )*SC_PITCH + m1] = acc[nt][2] + bo1;
        scf[(size_t)(n0+1)*SC_PITCH + m1] = acc[nt][3] + bo1;
    }
    __syncthreads();
    const int b = tid>>2, qq = tid&3;
    float* orow = out + (size_t)b*VV + vb;
    #pragma unroll
    for (int i=0;i<8;i++){
        const int f = qq*8 + i;
        *(float4*)&orow[f*4] = *(const float4*)&scf[(size_t)b*SC_PITCH + f*4];
    }

    // fused logsoftmax partial over this block's 128 v-columns
    {
        const float* rowp = &scf[(size_t)b*SC_PITCH + qq*32];
        float vm = rowp[0];
        #pragma unroll
        for (int i=1;i<32;i++) vm = fmaxf(vm, rowp[i]);
        vm = fmaxf(vm, __shfl_xor_sync(0xffffffffu, vm, 1));
        vm = fmaxf(vm, __shfl_xor_sync(0xffffffffu, vm, 2));
        float z = 0.f;
        #pragma unroll
        for (int i=0;i<32;i++) z += __expf(rowp[i] - vm);
        z += __shfl_xor_sync(0xffffffffu, z, 1);
        z += __shfl_xor_sync(0xffffffffu, z, 2);
        if (qq == 0){
            g_pm[(size_t)b*NLB + blockIdx.x] = vm;
            g_ps[(size_t)b*NLB + blockIdx.x] = z;
        }
    }
}

// ---------------------------------------------------------------------------
// Kernel 6: combine 250 (m,Z) partials + subtract lse. grid (64,4), 1024 thr.
// ---------------------------------------------------------------------------
__global__ __launch_bounds__(1024) void ls_norm(float* __restrict__ out)
{
    cudaGridDependencySynchronize();
    __shared__ float sm_[32], sz_[32];
    const int b = blockIdx.x, q = blockIdx.y;
    const int tid = threadIdx.x, lane = tid & 31, warp = tid >> 5;

    float m = -3.0e38f, z = 0.f;
    if (tid < NLB){
        m = g_pm[(size_t)b*NLB + tid];
        z = g_ps[(size_t)b*NLB + tid];
    }
    #pragma unroll
    for (int o=16;o;o>>=1){
        float om = __shfl_xor_sync(0xffffffffu, m, o);
        float oz = __shfl_xor_sync(0xffffffffu, z, o);
        float nm = fmaxf(m, om);
        z = z*__expf(m - nm) + oz*__expf(om - nm);
        m = nm;
    }
    if (lane==0){ sm_[warp] = m; sz_[warp] = z; }
    __syncthreads();
    if (warp==0){
        m = sm_[lane]; z = sz_[lane];
        #pragma unroll
        for (int o=16;o;o>>=1){
            float om = __shfl_xor_sync(0xffffffffu, m, o);
            float oz = __shfl_xor_sync(0xffffffffu, z, o);
            float nm = fmaxf(m, om);
            z = z*__expf(m - nm) + oz*__expf(om - nm);
            m = nm;
        }
        if (lane==0){ sm_[0] = m + logf(z); }
    }
    __syncthreads();
    const float lse = sm_[0];

    float* row = out + (size_t)b*VV + q*8000;
    #pragma unroll
    for (int j=0;j<2;j++){
        const int i4 = tid + j*1024;
        if (i4 < 2000){
            float4 v = *(const float4*)&row[i4*4];
            v.x -= lse; v.y -= lse; v.z -= lse; v.w -= lse;
            *(float4*)&row[i4*4] = v;
        }
    }
}

// ---------------------------------------------------------------------------
extern "C" void kernel_launch(void* const* d_in, const int* in_sizes, int n_in,
                              void* d_out, int out_size)
{
    const int*   input_batch = (const int*)  d_in[0];
    const float* prev_h      = (const float*)d_in[1];
    const float* prev_c      = (const float*)d_in[2];
    const float* enc         = (const float*)d_in[3];
    const int*   lengths     = (const int*)  d_in[4];
    const float* emb         = (const float*)d_in[5];
    const float* attn_w      = (const float*)d_in[6];
    const float* attn_b      = (const float*)d_in[7];
    const float* W_ih        = (const float*)d_in[8];
    const float* W_hh        = (const float*)d_in[9];
    const float* b_ih        = (const float*)d_in[10];
    const float* b_hh        = (const float*)d_in[11];
    const float* W_out       = (const float*)d_in[12];
    const float* b_out       = (const float*)d_in[13];
    float* out = (float*)d_out;

    cudaFuncSetAttribute(logits_gemm_ca, cudaFuncAttributeMaxDynamicSharedMemorySize, L_SMEM);
    cudaFuncSetAttribute(gates_gemm_ca,  cudaFuncAttributeMaxDynamicSharedMemorySize, GS_SMEM);

    cudaLaunchAttribute pdl[1];
    pdl[0].id = cudaLaunchAttributeProgrammaticStreamSerialization;
    pdl[0].val.programmaticStreamSerializationAllowed = 1;

    // k1: normal launch (no predecessor)
    attn_partial<<<dim3(64,4), 256>>>(prev_h, enc, attn_w, attn_b);

    // k2..k6: PDL launches
    {
        cudaLaunchConfig_t cfg = {};
        cfg.gridDim = dim3(64,1,1); cfg.blockDim = dim3(256,1,1);
        cfg.dynamicSmemBytes = 0; cfg.stream = 0;
        cfg.attrs = pdl; cfg.numAttrs = 1;
        cudaLaunchKernelEx(&cfg, attn_combine, input_batch, prev_h, emb, out);
    }
    {
        cudaLaunchConfig_t cfg = {};
        cfg.gridDim = dim3(32,KSPLIT,1); cfg.blockDim = dim3(256,1,1);
        cfg.dynamicSmemBytes = GS_SMEM; cfg.stream = 0;
        cfg.attrs = pdl; cfg.numAttrs = 1;
        cudaLaunchKernelEx(&cfg, gates_gemm_ca, W_ih, W_hh);
    }
    {
        cudaLaunchConfig_t cfg = {};
        cfg.gridDim = dim3(256,1,1); cfg.blockDim = dim3(256,1,1);
        cfg.dynamicSmemBytes = 0; cfg.stream = 0;
        cfg.attrs = pdl; cfg.numAttrs = 1;
        cudaLaunchKernelEx(&cfg, lstm_kernel, prev_c, lengths, b_ih, b_hh, out);
    }
    {
        cudaLaunchConfig_t cfg = {};
        cfg.gridDim = dim3(NLB,1,1); cfg.blockDim = dim3(256,1,1);
        cfg.dynamicSmemBytes = L_SMEM; cfg.stream = 0;
        cfg.attrs = pdl; cfg.numAttrs = 1;
        cudaLaunchKernelEx(&cfg, logits_gemm_ca, W_out, b_out, out);
    }
    {
        cudaLaunchConfig_t cfg = {};
        cfg.gridDim = dim3(64,4,1); cfg.blockDim = dim3(1024,1,1);
        cfg.dynamicSmemBytes = 0; cfg.stream = 0;
        cfg.attrs = pdl; cfg.numAttrs = 1;
        cudaLaunchKernelEx(&cfg, ls_norm, out);
    }
}